// round 1
// baseline (speedup 1.0000x reference)
#include <cuda_runtime.h>

#define SLEN    2048
#define BATCH   2
#define DMODEL  1024
#define HEADS   16
#define DK      64
#define MROWS   (SLEN*BATCH)          // 4096
#define NREL    (2*2048 - 1)          // 4095
#define SCALE_F 0.125f                // 1/sqrt(64)

// Scratch (no device allocation allowed -> __device__ globals)
__device__ float g_Q[BATCH*HEADS*SLEN*DK];     // [b,h,s,d] 16 MB
__device__ float g_K[BATCH*HEADS*SLEN*DK];
__device__ float g_V[BATCH*HEADS*SLEN*DK];
__device__ float g_ctx[MROWS*DMODEL];          // [s*B+b, h*64+d] 16 MB

// ---------------------------------------------------------------------------
// GEMM: out[m][n] = sum_k X[m][k] * W[n][k] + bias[n]
// M=4096, N=1024, K=1024. Tiles 128x128, KT=16, 256 threads, 8x8 per thread.
// DST: 0 = write to 'out' param (plain [m][n]); 1/2/3 = scatter into g_Q/g_K/g_V
//      as [b][h][s][d].
// SRC_CTX: read X from g_ctx instead of the param (host can't take &g_ctx).
// ---------------------------------------------------------------------------
template<int DST, bool SRC_CTX>
__global__ __launch_bounds__(256)
void gemm_xwT(const float* __restrict__ Xp, const float* __restrict__ W,
              const float* __restrict__ bias, float* __restrict__ out)
{
    __shared__ __align__(16) float Xs[16][132];   // [k][m] transposed
    __shared__ __align__(16) float Ws[16][132];   // [k][n] transposed

    const float* __restrict__ X = SRC_CTX ? g_ctx : Xp;

    const int tid = threadIdx.x;
    const int tx = tid & 15, ty = tid >> 4;
    const int m0 = blockIdx.y * 128;
    const int n0 = blockIdx.x * 128;

    float acc[8][8];
#pragma unroll
    for (int i = 0; i < 8; i++)
#pragma unroll
        for (int j = 0; j < 8; j++) acc[i][j] = 0.f;

    for (int kb = 0; kb < DMODEL; kb += 16) {
#pragma unroll
        for (int l = 0; l < 2; l++) {
            int f   = tid + l * 256;          // 0..511
            int row = f >> 2;                 // 0..127
            int ch  = f & 3;                  // 0..3 (float4 chunk in k)
            float4 xv = *(const float4*)&X[(size_t)(m0 + row) * DMODEL + kb + ch * 4];
            float4 wv = *(const float4*)&W[(size_t)(n0 + row) * DMODEL + kb + ch * 4];
            Xs[ch*4+0][row] = xv.x; Xs[ch*4+1][row] = xv.y;
            Xs[ch*4+2][row] = xv.z; Xs[ch*4+3][row] = xv.w;
            Ws[ch*4+0][row] = wv.x; Ws[ch*4+1][row] = wv.y;
            Ws[ch*4+2][row] = wv.z; Ws[ch*4+3][row] = wv.w;
        }
        __syncthreads();
#pragma unroll
        for (int k = 0; k < 16; k++) {
            float4 a0 = *(const float4*)&Xs[k][ty * 4];
            float4 a1 = *(const float4*)&Xs[k][64 + ty * 4];
            float4 b0 = *(const float4*)&Ws[k][tx * 4];
            float4 b1 = *(const float4*)&Ws[k][64 + tx * 4];
            float av[8] = {a0.x, a0.y, a0.z, a0.w, a1.x, a1.y, a1.z, a1.w};
            float bv[8] = {b0.x, b0.y, b0.z, b0.w, b1.x, b1.y, b1.z, b1.w};
#pragma unroll
            for (int i = 0; i < 8; i++)
#pragma unroll
                for (int j = 0; j < 8; j++)
                    acc[i][j] += av[i] * bv[j];
        }
        __syncthreads();
    }

    // epilogue: +bias, then store (float4 over n; d stays within one head)
#pragma unroll
    for (int i = 0; i < 8; i++) {
        int m = m0 + ((i < 4) ? (ty * 4 + i) : (64 + ty * 4 + i - 4));
#pragma unroll
        for (int jb = 0; jb < 2; jb++) {
            int nb = n0 + ((jb == 0) ? (tx * 4) : (64 + tx * 4));
            float4 v;
            v.x = acc[i][jb*4+0] + bias[nb + 0];
            v.y = acc[i][jb*4+1] + bias[nb + 1];
            v.z = acc[i][jb*4+2] + bias[nb + 2];
            v.w = acc[i][jb*4+3] + bias[nb + 3];
            if (DST == 0) {
                *(float4*)&out[(size_t)m * DMODEL + nb] = v;
            } else {
                int s = m >> 1, b = m & 1;
                int h = nb >> 6, d = nb & 63;
                float* dstbuf = (DST == 1) ? g_Q : (DST == 2) ? g_K : g_V;
                *(float4*)&dstbuf[(((size_t)(b * HEADS + h) * SLEN + s) * DK) + d] = v;
            }
        }
    }
}

// ---------------------------------------------------------------------------
// Flash-style attention with relative-position bias.
// Grid: (SLEN/64 q-tiles, B*H). Block: 256 threads (16x16), 4x4 per thread.
// Per block: Q tile 64x64 in smem; loop 32 K/V tiles of 64 rows:
//   S = Q K^T * scale + relbias ; online softmax ; O += P V.
// Smem: Qs 16KB + Kt(=Ps alias) 16KB + Vs 16KB = 48KB static (no opt-in needed).
// Rel bias: each thread only needs table[(q-k)+2047] for 7 distinct (i-c)
// offsets per tile -> 7 LDG from the 256KB L2-resident table, no smem stage.
// ---------------------------------------------------------------------------
__global__ __launch_bounds__(256)
void attn_kernel(const float* __restrict__ rel_table)
{
    __shared__ __align__(16) float Qs[64][64];
    __shared__ __align__(16) float KtPs[64][64];  // K transposed [d][c]; later P [r][c]
    __shared__ __align__(16) float Vs[64][64];    // [c][vc]

    const int tid = threadIdx.x;
    const int tx = tid & 15, ty = tid >> 4;
    const int q0 = blockIdx.x * 64;
    const int bh = blockIdx.y;
    const int h  = bh & (HEADS - 1);
    const int b  = bh >> 4;
    const float* Qp = g_Q + (size_t)bh * SLEN * DK;
    const float* Kp = g_K + (size_t)bh * SLEN * DK;
    const float* Vp = g_V + (size_t)bh * SLEN * DK;

    // load Q tile (row-major, 4 float4 per thread)
#pragma unroll
    for (int l = 0; l < 4; l++) {
        int f = tid + l * 256;
        int r = f >> 4, ch = f & 15;
        *(float4*)&Qs[r][ch * 4] =
            *(const float4*)&Qp[(size_t)(q0 + r) * DK + ch * 4];
    }

    float m_run[4], l_run[4], o[4][4];
#pragma unroll
    for (int i = 0; i < 4; i++) {
        m_run[i] = -1e30f; l_run[i] = 0.f;
#pragma unroll
        for (int j = 0; j < 4; j++) o[i][j] = 0.f;
    }

    for (int k0 = 0; k0 < SLEN; k0 += 64) {
        // load K (transposed into smem) and V (row-major)
#pragma unroll
        for (int l = 0; l < 4; l++) {
            int f = tid + l * 256;
            int r = f >> 4, ch = f & 15;
            float4 kv = *(const float4*)&Kp[(size_t)(k0 + r) * DK + ch * 4];
            KtPs[ch*4+0][r] = kv.x; KtPs[ch*4+1][r] = kv.y;
            KtPs[ch*4+2][r] = kv.z; KtPs[ch*4+3][r] = kv.w;
            *(float4*)&Vs[r][ch * 4] =
                *(const float4*)&Vp[(size_t)(k0 + r) * DK + ch * 4];
        }
        // rel bias: 7 values cover all (i-c) in [-3,3] for this thread/tile
        float relv[7];
        {
            int base = (q0 - k0) + (ty - tx) * 4 + (NREL / 2); // +2047
#pragma unroll
            for (int dd = 0; dd < 7; dd++) {
                int idx = base + dd - 3;
                idx = min(max(idx, 0), NREL - 1);
                relv[dd] = __ldg(&rel_table[idx * HEADS + h]);
            }
        }
        __syncthreads();

        // S = Q K^T (4x4 per thread)
        float s[4][4];
#pragma unroll
        for (int i = 0; i < 4; i++)
#pragma unroll
            for (int j = 0; j < 4; j++) s[i][j] = 0.f;
#pragma unroll
        for (int dc = 0; dc < 16; dc++) {
            float qv[4][4], kv[4][4];
#pragma unroll
            for (int i = 0; i < 4; i++) {
                float4 t = *(const float4*)&Qs[ty * 4 + i][dc * 4];
                qv[i][0] = t.x; qv[i][1] = t.y; qv[i][2] = t.z; qv[i][3] = t.w;
            }
#pragma unroll
            for (int j = 0; j < 4; j++) {
                float4 t = *(const float4*)&KtPs[dc * 4 + j][tx * 4];
                kv[j][0] = t.x; kv[j][1] = t.y; kv[j][2] = t.z; kv[j][3] = t.w;
            }
#pragma unroll
            for (int i = 0; i < 4; i++)
#pragma unroll
                for (int j = 0; j < 4; j++)
#pragma unroll
                    for (int c = 0; c < 4; c++)
                        s[i][c] += qv[i][j] * kv[j][c];
        }

        // scale + bias, online softmax update
#pragma unroll
        for (int i = 0; i < 4; i++) {
            float mx = -1e30f;
#pragma unroll
            for (int c = 0; c < 4; c++) {
                float v = s[i][c] * SCALE_F + relv[i - c + 3];
                s[i][c] = v;
                mx = fmaxf(mx, v);
            }
#pragma unroll
            for (int w = 8; w >= 1; w >>= 1)
                mx = fmaxf(mx, __shfl_xor_sync(0xffffffffu, mx, w));
            float m_new = fmaxf(m_run[i], mx);
            float sum = 0.f;
#pragma unroll
            for (int c = 0; c < 4; c++) {
                float p = __expf(s[i][c] - m_new);
                s[i][c] = p;
                sum += p;
            }
#pragma unroll
            for (int w = 8; w >= 1; w >>= 1)
                sum += __shfl_xor_sync(0xffffffffu, sum, w);
            float alpha = __expf(m_run[i] - m_new);
            l_run[i] = l_run[i] * alpha + sum;
            m_run[i] = m_new;
#pragma unroll
            for (int j = 0; j < 4; j++) o[i][j] *= alpha;
        }

        __syncthreads();   // all K-transpose reads done before P overwrites it
#pragma unroll
        for (int i = 0; i < 4; i++) {
            float4 v = make_float4(s[i][0], s[i][1], s[i][2], s[i][3]);
            *(float4*)&KtPs[ty * 4 + i][tx * 4] = v;   // now P[r][c]
        }
        __syncthreads();

        // O += P V (4x4 per thread)
#pragma unroll
        for (int cc = 0; cc < 16; cc++) {
            float pv[4][4], vv[4][4];
#pragma unroll
            for (int i = 0; i < 4; i++) {
                float4 t = *(const float4*)&KtPs[ty * 4 + i][cc * 4];
                pv[i][0] = t.x; pv[i][1] = t.y; pv[i][2] = t.z; pv[i][3] = t.w;
            }
#pragma unroll
            for (int j = 0; j < 4; j++) {
                float4 t = *(const float4*)&Vs[cc * 4 + j][tx * 4];
                vv[j][0] = t.x; vv[j][1] = t.y; vv[j][2] = t.z; vv[j][3] = t.w;
            }
#pragma unroll
            for (int i = 0; i < 4; i++)
#pragma unroll
                for (int j = 0; j < 4; j++)
#pragma unroll
                    for (int c = 0; c < 4; c++)
                        o[i][c] += pv[i][j] * vv[j][c];
        }
        __syncthreads();   // P/V reads done before next tile overwrites
    }

    // normalize and write ctx[(s*B+b)][h*64+vc]
#pragma unroll
    for (int i = 0; i < 4; i++) {
        float inv = 1.f / l_run[i];
        int srow = q0 + ty * 4 + i;
        float4 v = make_float4(o[i][0] * inv, o[i][1] * inv,
                               o[i][2] * inv, o[i][3] * inv);
        *(float4*)&g_ctx[(size_t)(srow * BATCH + b) * DMODEL + h * DK + tx * 4] = v;
    }
}

// ---------------------------------------------------------------------------
extern "C" void kernel_launch(void* const* d_in, const int* in_sizes, int n_in,
                              void* d_out, int out_size)
{
    const float* query = (const float*)d_in[0];
    const float* key   = (const float*)d_in[1];
    const float* value = (const float*)d_in[2];
    const float* Wq    = (const float*)d_in[3];
    const float* bq    = (const float*)d_in[4];
    const float* Wk    = (const float*)d_in[5];
    const float* bk    = (const float*)d_in[6];
    const float* Wv    = (const float*)d_in[7];
    const float* bv    = (const float*)d_in[8];
    const float* Wo    = (const float*)d_in[9];
    const float* bo    = (const float*)d_in[10];
    const float* rel   = (const float*)d_in[11];
    float* out = (float*)d_out;

    dim3 gg(DMODEL / 128, MROWS / 128);   // (8, 32)
    dim3 bb(256);

    gemm_xwT<1, false><<<gg, bb>>>(query, Wq, bq, nullptr);   // -> g_Q
    gemm_xwT<2, false><<<gg, bb>>>(key,   Wk, bk, nullptr);   // -> g_K
    gemm_xwT<3, false><<<gg, bb>>>(value, Wv, bv, nullptr);   // -> g_V

    attn_kernel<<<dim3(SLEN / 64, BATCH * HEADS), 256>>>(rel); // -> g_ctx

    gemm_xwT<0, true><<<gg, bb>>>(nullptr, Wo, bo, out);      // ctx @ Wo^T + bo
}

// round 2
// speedup vs baseline: 1.2442x; 1.2442x over previous
#include <cuda_runtime.h>
#include <mma.h>
using namespace nvcuda;

#define SLEN    2048
#define BATCH   2
#define DMODEL  1024
#define HEADS   16
#define DK      64
#define MROWS   (SLEN*BATCH)          // 4096
#define NREL    (2*2048 - 1)          // 4095
#define SCALE_F 0.125f                // 1/sqrt(64)

// Scratch (no device allocation allowed -> __device__ globals)
// All in "row" layout [m = s*BATCH + b][n = h*64 + d]
__device__ float g_Q[MROWS*DMODEL];
__device__ float g_K[MROWS*DMODEL];
__device__ float g_V[MROWS*DMODEL];
__device__ float g_ctx[MROWS*DMODEL];

// ---------------------------------------------------------------------------
// tf32 WMMA GEMM: out[m][n] = sum_k X[m][k]*W[n][k] + bias[n]
// M=4096, N=1024, K=1024. Block 128x128, KT=32, 256 thr (8 warps),
// warp tile 32x64 (2x4 of 16x16x8 wmma frags).
// ---------------------------------------------------------------------------
__global__ __launch_bounds__(256)
void gemm_tf32(const float* __restrict__ X, const float* __restrict__ W,
               const float* __restrict__ bias, float* __restrict__ out)
{
    __shared__ __align__(16) float sm[2*128*36];   // Xs | Ws ; aliased by epilogue
    float (*Xs)[36] = (float(*)[36])sm;
    float (*Ws)[36] = (float(*)[36])(sm + 128*36);

    const int tid  = threadIdx.x;
    const int wid  = tid >> 5, lane = tid & 31;
    const int wm   = wid >> 1;           // 0..3 (32 rows each)
    const int wn   = wid & 1;            // 0..1 (64 cols each)
    const int m0   = blockIdx.y * 128;
    const int n0   = blockIdx.x * 128;

    wmma::fragment<wmma::accumulator,16,16,8,float> acc[2][4];
#pragma unroll
    for (int mi = 0; mi < 2; mi++)
#pragma unroll
        for (int ni = 0; ni < 4; ni++) wmma::fill_fragment(acc[mi][ni], 0.f);

    for (int kb = 0; kb < DMODEL; kb += 32) {
#pragma unroll
        for (int l = 0; l < 4; l++) {
            int f = tid + l * 256;             // 0..1023
            int row = f >> 3, c4 = f & 7;      // 128 rows x 8 float4
            *(float4*)&Xs[row][c4*4] =
                *(const float4*)&X[(size_t)(m0 + row) * DMODEL + kb + c4*4];
            *(float4*)&Ws[row][c4*4] =
                *(const float4*)&W[(size_t)(n0 + row) * DMODEL + kb + c4*4];
        }
        __syncthreads();
#pragma unroll
        for (int ks = 0; ks < 4; ks++) {
            wmma::fragment<wmma::matrix_a,16,16,8,wmma::precision::tf32,wmma::row_major> a[2];
            wmma::fragment<wmma::matrix_b,16,16,8,wmma::precision::tf32,wmma::col_major> bfr[4];
#pragma unroll
            for (int mi = 0; mi < 2; mi++) {
                wmma::load_matrix_sync(a[mi], &Xs[wm*32 + mi*16][ks*8], 36);
#pragma unroll
                for (int t = 0; t < a[mi].num_elements; t++)
                    a[mi].x[t] = wmma::__float_to_tf32(a[mi].x[t]);
            }
#pragma unroll
            for (int ni = 0; ni < 4; ni++) {
                wmma::load_matrix_sync(bfr[ni], &Ws[wn*64 + ni*16][ks*8], 36);
#pragma unroll
                for (int t = 0; t < bfr[ni].num_elements; t++)
                    bfr[ni].x[t] = wmma::__float_to_tf32(bfr[ni].x[t]);
            }
#pragma unroll
            for (int mi = 0; mi < 2; mi++)
#pragma unroll
                for (int ni = 0; ni < 4; ni++)
                    wmma::mma_sync(acc[mi][ni], a[mi], bfr[ni], acc[mi][ni]);
        }
        __syncthreads();
    }

    // Epilogue: stage each warp's 16x64 row-block in smem, add bias, store.
    float (*patch)[64] = (float(*)[64])(sm + wid * 16 * 64);
#pragma unroll
    for (int mi = 0; mi < 2; mi++) {
#pragma unroll
        for (int ni = 0; ni < 4; ni++)
            wmma::store_matrix_sync(&patch[0][ni*16], acc[mi][ni], 64, wmma::mem_row_major);
        __syncwarp();
#pragma unroll
        for (int l = 0; l < 8; l++) {
            int f = lane + l * 32;             // 0..255
            int r = f >> 4, c4 = f & 15;       // 16 rows x 16 float4
            int m = m0 + wm*32 + mi*16 + r;
            int n = n0 + wn*64 + c4*4;
            float4 v = *(float4*)&patch[r][c4*4];
            float4 bb = *(const float4*)&bias[n];
            v.x += bb.x; v.y += bb.y; v.z += bb.z; v.w += bb.w;
            *(float4*)&out[(size_t)m * DMODEL + n] = v;
        }
        __syncwarp();
    }
}

// ---------------------------------------------------------------------------
// Flash attention with relative bias, tf32 WMMA for QK^T and PV.
// Grid (32 q-tiles, 32 bh). Block 128 thr (4 warps, warp w owns q-rows
// [w*16, w*16+16)). Dynamic smem: Qs|Ks|Vs|Ss (each 64x68 f32) + bias[128].
// O accumulated in registers: 2 threads per row x 32 cols each.
// ---------------------------------------------------------------------------
#define ALD 68
#define ATILE (64*ALD)

__global__ __launch_bounds__(128)
void attn_kernel(const float* __restrict__ rel_table)
{
    extern __shared__ __align__(16) float smA[];
    float (*Qs)[ALD] = (float(*)[ALD])smA;
    float (*Ks)[ALD] = (float(*)[ALD])(smA + ATILE);       // K, then PV result
    float (*Vs)[ALD] = (float(*)[ALD])(smA + 2*ATILE);
    float (*Ss)[ALD] = (float(*)[ALD])(smA + 3*ATILE);     // S, then P
    float *sbias     = smA + 4*ATILE;                       // 127 used

    const int tid = threadIdx.x;
    const int wid = tid >> 5;
    const int q0  = blockIdx.x * 64;
    const int bh  = blockIdx.y;
    const int h   = bh & (HEADS - 1);
    const int b   = bh >> 4;
    const int col0 = h * DK;

    // load Q tile: rows m=(q0+r)*2+b, cols col0..col0+63
#pragma unroll
    for (int l = 0; l < 8; l++) {
        int f = tid + l * 128;
        int r = f >> 4, c4 = f & 15;
        *(float4*)&Qs[r][c4*4] =
            *(const float4*)&g_Q[(size_t)((q0 + r)*BATCH + b) * DMODEL + col0 + c4*4];
    }

    const int r_own = tid >> 1;           // 0..63
    const int ch    = (tid & 1) * 32;     // column half
    float m_run = -1e30f, l_run = 0.f;
    float o[32];
#pragma unroll
    for (int j = 0; j < 32; j++) o[j] = 0.f;

    for (int k0 = 0; k0 < SLEN; k0 += 64) {
        // load K, V tiles
#pragma unroll
        for (int l = 0; l < 8; l++) {
            int f = tid + l * 128;
            int r = f >> 4, c4 = f & 15;
            size_t gofs = (size_t)((k0 + r)*BATCH + b) * DMODEL + col0 + c4*4;
            *(float4*)&Ks[r][c4*4] = *(const float4*)&g_K[gofs];
            *(float4*)&Vs[r][c4*4] = *(const float4*)&g_V[gofs];
        }
        // bias vector: sbias[t] = table[clip(q0-k0 + t-63 + 2047)][h], t in [0,126]
        if (tid < 127) {
            int idx = q0 - k0 + tid - 63 + (NREL / 2);
            idx = min(max(idx, 0), NREL - 1);
            sbias[tid] = __ldg(&rel_table[idx * HEADS + h]);
        }
        __syncthreads();

        // S = Q K^T  (warp: 16 rows x 64 cols)
        wmma::fragment<wmma::accumulator,16,16,8,float> sacc[4];
#pragma unroll
        for (int ni = 0; ni < 4; ni++) wmma::fill_fragment(sacc[ni], 0.f);
#pragma unroll
        for (int kc = 0; kc < 8; kc++) {
            wmma::fragment<wmma::matrix_a,16,16,8,wmma::precision::tf32,wmma::row_major> a;
            wmma::load_matrix_sync(a, &Qs[wid*16][kc*8], ALD);
#pragma unroll
            for (int t = 0; t < a.num_elements; t++) a.x[t] = wmma::__float_to_tf32(a.x[t]);
#pragma unroll
            for (int ni = 0; ni < 4; ni++) {
                wmma::fragment<wmma::matrix_b,16,16,8,wmma::precision::tf32,wmma::col_major> bf;
                wmma::load_matrix_sync(bf, &Ks[ni*16][kc*8], ALD);
#pragma unroll
                for (int t = 0; t < bf.num_elements; t++) bf.x[t] = wmma::__float_to_tf32(bf.x[t]);
                wmma::mma_sync(sacc[ni], a, bf, sacc[ni]);
            }
        }
#pragma unroll
        for (int ni = 0; ni < 4; ni++)
            wmma::store_matrix_sync(&Ss[wid*16][ni*16], sacc[ni], ALD, wmma::mem_row_major);
        __syncthreads();

        // online softmax (2 threads per row, 32 cols each)
        float v[32];
        float mx = -1e30f;
#pragma unroll
        for (int j = 0; j < 32; j++) {
            int c = ch + j;
            float val = Ss[r_own][c] * SCALE_F + sbias[r_own - c + 63];
            v[j] = val;
            mx = fmaxf(mx, val);
        }
        mx = fmaxf(mx, __shfl_xor_sync(0xffffffffu, mx, 1));
        float m_new = fmaxf(m_run, mx);
        float ssum = 0.f;
#pragma unroll
        for (int j = 0; j < 32; j++) {
            v[j] = __expf(v[j] - m_new);
            ssum += v[j];
        }
        ssum += __shfl_xor_sync(0xffffffffu, ssum, 1);
        float alpha = __expf(m_run - m_new);
        l_run = l_run * alpha + ssum;
        m_run = m_new;
#pragma unroll
        for (int j = 0; j < 32; j++) Ss[r_own][ch + j] = v[j];
        __syncthreads();

        // PV: O_tile = P @ V  -> store into Ks region (K no longer needed)
        wmma::fragment<wmma::accumulator,16,16,8,float> pvacc[4];
#pragma unroll
        for (int ni = 0; ni < 4; ni++) wmma::fill_fragment(pvacc[ni], 0.f);
#pragma unroll
        for (int kc = 0; kc < 8; kc++) {
            wmma::fragment<wmma::matrix_a,16,16,8,wmma::precision::tf32,wmma::row_major> a;
            wmma::load_matrix_sync(a, &Ss[wid*16][kc*8], ALD);
#pragma unroll
            for (int t = 0; t < a.num_elements; t++) a.x[t] = wmma::__float_to_tf32(a.x[t]);
#pragma unroll
            for (int ni = 0; ni < 4; ni++) {
                wmma::fragment<wmma::matrix_b,16,16,8,wmma::precision::tf32,wmma::row_major> bf;
                wmma::load_matrix_sync(bf, &Vs[kc*8][ni*16], ALD);
#pragma unroll
                for (int t = 0; t < bf.num_elements; t++) bf.x[t] = wmma::__float_to_tf32(bf.x[t]);
                wmma::mma_sync(pvacc[ni], a, bf, pvacc[ni]);
            }
        }
#pragma unroll
        for (int ni = 0; ni < 4; ni++)
            wmma::store_matrix_sync(&Ks[wid*16][ni*16], pvacc[ni], ALD, wmma::mem_row_major);
        __syncthreads();

        // accumulate into register O
#pragma unroll
        for (int j = 0; j < 32; j++)
            o[j] = o[j] * alpha + Ks[r_own][ch + j];
        __syncthreads();   // before next tile overwrites Ks/Vs/Ss
    }

    // normalize + write ctx[(q)*B+b][h*64 + c]
    float inv = 1.f / l_run;
    size_t base = (size_t)((q0 + r_own)*BATCH + b) * DMODEL + col0 + ch;
#pragma unroll
    for (int j4 = 0; j4 < 8; j4++) {
        float4 vv = make_float4(o[j4*4+0]*inv, o[j4*4+1]*inv,
                                o[j4*4+2]*inv, o[j4*4+3]*inv);
        *(float4*)&g_ctx[base + j4*4] = vv;
    }
}

// ---------------------------------------------------------------------------
extern "C" void kernel_launch(void* const* d_in, const int* in_sizes, int n_in,
                              void* d_out, int out_size)
{
    const float* query = (const float*)d_in[0];
    const float* key   = (const float*)d_in[1];
    const float* value = (const float*)d_in[2];
    const float* Wq    = (const float*)d_in[3];
    const float* bq    = (const float*)d_in[4];
    const float* Wk    = (const float*)d_in[5];
    const float* bk    = (const float*)d_in[6];
    const float* Wv    = (const float*)d_in[7];
    const float* bv    = (const float*)d_in[8];
    const float* Wo    = (const float*)d_in[9];
    const float* bo    = (const float*)d_in[10];
    const float* rel   = (const float*)d_in[11];
    float* out = (float*)d_out;

    float *pQ, *pK, *pV, *pC;
    cudaGetSymbolAddress((void**)&pQ, g_Q);
    cudaGetSymbolAddress((void**)&pK, g_K);
    cudaGetSymbolAddress((void**)&pV, g_V);
    cudaGetSymbolAddress((void**)&pC, g_ctx);

    const int attn_smem = (4*ATILE + 128) * (int)sizeof(float);   // ~70.2 KB
    cudaFuncSetAttribute(attn_kernel, cudaFuncAttributeMaxDynamicSharedMemorySize, attn_smem);

    dim3 gg(DMODEL / 128, MROWS / 128);   // (8, 32)
    dim3 bb(256);

    gemm_tf32<<<gg, bb>>>(query, Wq, bq, pQ);
    gemm_tf32<<<gg, bb>>>(key,   Wk, bk, pK);
    gemm_tf32<<<gg, bb>>>(value, Wv, bv, pV);

    attn_kernel<<<dim3(SLEN/64, BATCH*HEADS), 128, attn_smem>>>(rel);

    gemm_tf32<<<gg, bb>>>(pC, Wo, bo, out);
}

// round 4
// speedup vs baseline: 2.7842x; 2.2378x over previous
#include <cuda_runtime.h>
#include <cuda_fp16.h>
#include <mma.h>
#include <cstdint>
using namespace nvcuda;

#define SLEN    2048
#define BATCH   2
#define DMODEL  1024
#define HEADS   16
#define DK      64
#define MROWS   (SLEN*BATCH)          // 4096
#define NREL    (2*2048 - 1)          // 4095
#define SCALE_F 0.125f                // 1/sqrt(64)
#define EXP_OFF 12.0f                 // fixed softmax offset (cancels in normalization)

// Scratch (no device allocation allowed -> __device__ globals). fp16, layout
// [m = s*BATCH + b][n = h*64 + d]
__device__ __half g_Q[MROWS*DMODEL];
__device__ __half g_K[MROWS*DMODEL];
__device__ __half g_V[MROWS*DMODEL];
__device__ __half g_ctx[MROWS*DMODEL];

// ===========================================================================
// fp16 WMMA GEMM: out[m][n] = sum_k X[m][k]*W[n][k] + bias[n]
// M=4096, N=1024, K=1024. Block tile 128x128, KT=32 (2 x k16 steps),
// 256 thr (8 warps), warp tile 32x64. Register-prefetch pipeline.
// OUT_HALF: 1 -> write __half scratch, 0 -> write float out.
// SRC_HALF: 1 -> X is __half (g_ctx), 0 -> X is float.
// ===========================================================================
#define GLD 40          // half stride of smem tiles (80B, ldmatrix conflict-free)

template<int OUT_HALF, int SRC_HALF>
__global__ __launch_bounds__(256)
void gemm_f16(const void* __restrict__ Xv, const float* __restrict__ W,
              const float* __restrict__ bias, void* __restrict__ outv)
{
    // union: loader tiles (20480B) | epilogue patches (34816B)
    __shared__ __align__(16) char smraw[8*16*68*4];
    __half* Xs = (__half*)smraw;                   // [128][GLD]
    __half* Ws = (__half*)(smraw + 128*GLD*2);     // [128][GLD]
    float*  patch = (float*)smraw;                 // [8 warps][16][68]

    const int tid  = threadIdx.x;
    const int wid  = tid >> 5, lane = tid & 31;
    const int wm   = wid >> 1;            // 0..3
    const int wn   = wid & 1;             // 0..1
    const int m0   = blockIdx.y * 128;
    const int n0   = blockIdx.x * 128;

    const float*  Xf = (const float*)Xv;
    const __half* Xh = (const __half*)Xv;

    wmma::fragment<wmma::accumulator,16,16,16,float> acc[2][4];
#pragma unroll
    for (int mi = 0; mi < 2; mi++)
#pragma unroll
        for (int ni = 0; ni < 4; ni++) wmma::fill_fragment(acc[mi][ni], 0.f);

    // loader coords
    const int row = tid >> 1;             // 0..127
    const int u0  = (tid & 1) * 4;        // float4 chunk base (f32 src)
    const int uh0 = (tid & 1) * 2;        // uint4(8 half) chunk base (half src)

    float4 px[4], pw[4];
    uint4  hx[2];

    auto prefetch = [&](int it) {
        if (SRC_HALF) {
#pragma unroll
            for (int c = 0; c < 2; c++)
                hx[c] = *(const uint4*)&Xh[(size_t)(m0 + row) * DMODEL + it*32 + (uh0 + c)*8];
        } else {
#pragma unroll
            for (int c = 0; c < 4; c++)
                px[c] = *(const float4*)&Xf[(size_t)(m0 + row) * DMODEL + it*32 + (u0 + c)*4];
        }
#pragma unroll
        for (int c = 0; c < 4; c++)
            pw[c] = *(const float4*)&W[(size_t)(n0 + row) * DMODEL + it*32 + (u0 + c)*4];
    };

    prefetch(0);
    const int NIT = DMODEL / 32;          // 32
    for (int it = 0; it < NIT; it++) {
        __syncthreads();                  // prev-stage smem consumers done
        // store stage to smem (cvt f32->half where needed)
        if (SRC_HALF) {
#pragma unroll
            for (int c = 0; c < 2; c++)
                *(uint4*)&Xs[row*GLD + (uh0 + c)*8] = hx[c];
        } else {
#pragma unroll
            for (int c = 0; c < 4; c++) {
                __half2 a = __floats2half2_rn(px[c].x, px[c].y);
                __half2 b = __floats2half2_rn(px[c].z, px[c].w);
                *(__half2*)&Xs[row*GLD + (u0 + c)*4]     = a;
                *(__half2*)&Xs[row*GLD + (u0 + c)*4 + 2] = b;
            }
        }
#pragma unroll
        for (int c = 0; c < 4; c++) {
            __half2 a = __floats2half2_rn(pw[c].x, pw[c].y);
            __half2 b = __floats2half2_rn(pw[c].z, pw[c].w);
            *(__half2*)&Ws[row*GLD + (u0 + c)*4]     = a;
            *(__half2*)&Ws[row*GLD + (u0 + c)*4 + 2] = b;
        }
        __syncthreads();
        if (it + 1 < NIT) prefetch(it + 1);    // LDG in flight during mma

#pragma unroll
        for (int ks = 0; ks < 2; ks++) {
            wmma::fragment<wmma::matrix_a,16,16,16,__half,wmma::row_major> a[2];
            wmma::fragment<wmma::matrix_b,16,16,16,__half,wmma::col_major> bf[4];
#pragma unroll
            for (int mi = 0; mi < 2; mi++)
                wmma::load_matrix_sync(a[mi], &Xs[(wm*32 + mi*16)*GLD + ks*16], GLD);
#pragma unroll
            for (int ni = 0; ni < 4; ni++)
                wmma::load_matrix_sync(bf[ni], &Ws[(wn*64 + ni*16)*GLD + ks*16], GLD);
#pragma unroll
            for (int mi = 0; mi < 2; mi++)
#pragma unroll
                for (int ni = 0; ni < 4; ni++)
                    wmma::mma_sync(acc[mi][ni], a[mi], bf[ni], acc[mi][ni]);
        }
    }
    __syncthreads();   // loader tiles dead; reuse smem as patches

    float* pp = patch + wid * 16 * 68;
#pragma unroll
    for (int mi = 0; mi < 2; mi++) {
#pragma unroll
        for (int ni = 0; ni < 4; ni++)
            wmma::store_matrix_sync(pp + ni*16, acc[mi][ni], 68, wmma::mem_row_major);
        __syncwarp();
#pragma unroll
        for (int l = 0; l < 8; l++) {
            int f = lane + l * 32;             // 0..255
            int r = f >> 4, c4 = f & 15;       // 16 rows x 16 float4
            int m = m0 + wm*32 + mi*16 + r;
            int n = n0 + wn*64 + c4*4;
            float4 v = *(float4*)&pp[r*68 + c4*4];
            float4 bb = *(const float4*)&bias[n];
            v.x += bb.x; v.y += bb.y; v.z += bb.z; v.w += bb.w;
            if (OUT_HALF) {
                __half2 h0 = __floats2half2_rn(v.x, v.y);
                __half2 h1 = __floats2half2_rn(v.z, v.w);
                uint2 u; u.x = *(uint32_t*)&h0; u.y = *(uint32_t*)&h1;
                *(uint2*)&((__half*)outv)[(size_t)m * DMODEL + n] = u;
            } else {
                *(float4*)&((float*)outv)[(size_t)m * DMODEL + n] = v;
            }
        }
        __syncwarp();
    }
}

// ===========================================================================
// Flash attention, fp16 wmma, fixed-offset softmax (no online rescale).
// Grid (16 q-tiles of 128 rows, 32 bh). Block 256 thr (8 warps x 16 rows).
// O accumulated in persistent wmma accumulator fragments across K tiles.
// Smem (dynamic, 90880B): Qs/Ps half[128][72], Ks/Vs half[64][72],
//                         Ss f32[128][68], bias f32[192].
// ===========================================================================
#define AQ_LD 72
#define AS_LD 68
#define QS_OFF 0
#define KS_OFF 18432
#define VS_OFF 27648
#define PS_OFF 36864
#define SS_OFF 55296
#define SB_OFF 90112
#define ATTN_SMEM 90880

__global__ __launch_bounds__(256)
void attn_kernel(const float* __restrict__ rel_table)
{
    extern __shared__ __align__(16) char sm[];
    __half* Qs = (__half*)(sm + QS_OFF);   // [128][72]
    __half* Ks = (__half*)(sm + KS_OFF);   // [64][72]
    __half* Vs = (__half*)(sm + VS_OFF);   // [64][72]
    __half* Ps = (__half*)(sm + PS_OFF);   // [128][72]
    float*  Ss = (float*)(sm + SS_OFF);    // [128][68]
    float*  sb = (float*)(sm + SB_OFF);    // [192]

    const int tid = threadIdx.x;
    const int wid = tid >> 5;
    const int q0  = blockIdx.x * 128;
    const int bh  = blockIdx.y;
    const int h   = bh & (HEADS - 1);
    const int b   = bh >> 4;
    const int col0 = h * DK;

    // load Q tile once: 128 rows x 64 halves
    {
        int r = tid >> 1;
        int u0 = (tid & 1) * 4;
#pragma unroll
        for (int c = 0; c < 4; c++) {
            *(uint4*)&Qs[r*AQ_LD + (u0 + c)*8] =
                *(const uint4*)&g_Q[(size_t)((q0 + r)*BATCH + b) * DMODEL + col0 + (u0 + c)*8];
        }
    }

    wmma::fragment<wmma::accumulator,16,16,16,float> pvacc[4];
#pragma unroll
    for (int ni = 0; ni < 4; ni++) wmma::fill_fragment(pvacc[ni], 0.f);

    const int s_r  = tid >> 1;           // softmax row owner
    const int s_c0 = (tid & 1) * 32;     // column half
    float lrun = 0.f;

    for (int k0 = 0; k0 < SLEN; k0 += 64) {
        // load K, V tiles (64 rows x 64 halves each)
        {
            int r = tid >> 2;
            int u0 = (tid & 3) * 2;
#pragma unroll
            for (int c = 0; c < 2; c++) {
                size_t g = (size_t)((k0 + r)*BATCH + b) * DMODEL + col0 + (u0 + c)*8;
                *(uint4*)&Ks[r*AQ_LD + (u0 + c)*8] = *(const uint4*)&g_K[g];
                *(uint4*)&Vs[r*AQ_LD + (u0 + c)*8] = *(const uint4*)&g_V[g];
            }
        }
        if (tid < 191) {
            int idx = (q0 - k0) + tid - 63 + (NREL / 2);
            idx = min(max(idx, 0), NREL - 1);
            sb[tid] = __ldg(&rel_table[idx * HEADS + h]);
        }
        __syncthreads();

        // S = Q K^T : warp covers 16 q-rows x 64 k-cols
        wmma::fragment<wmma::accumulator,16,16,16,float> sacc[4];
#pragma unroll
        for (int ni = 0; ni < 4; ni++) wmma::fill_fragment(sacc[ni], 0.f);
#pragma unroll
        for (int kc = 0; kc < 4; kc++) {
            wmma::fragment<wmma::matrix_a,16,16,16,__half,wmma::row_major> a;
            wmma::load_matrix_sync(a, &Qs[(wid*16)*AQ_LD + kc*16], AQ_LD);
#pragma unroll
            for (int ni = 0; ni < 4; ni++) {
                wmma::fragment<wmma::matrix_b,16,16,16,__half,wmma::col_major> bf;
                wmma::load_matrix_sync(bf, &Ks[(ni*16)*AQ_LD + kc*16], AQ_LD);
                wmma::mma_sync(sacc[ni], a, bf, sacc[ni]);
            }
        }
#pragma unroll
        for (int ni = 0; ni < 4; ni++)
            wmma::store_matrix_sync(&Ss[(wid*16)*AS_LD + ni*16], sacc[ni], AS_LD, wmma::mem_row_major);
        __syncthreads();

        // fixed-offset softmax: p = exp(s*scale + bias - 12); l += p
#pragma unroll
        for (int j = 0; j < 32; j++) {
            int c = s_c0 + j;
            float val = Ss[s_r*AS_LD + c] * SCALE_F + sb[s_r - c + 63];
            float p = __expf(val - EXP_OFF);
            __half hp = __float2half_rn(p);
            lrun += __half2float(hp);          // normalize with the value PV actually uses
            Ps[s_r*AQ_LD + c] = hp;
        }
        __syncthreads();

        // O += P V  (accumulates directly into persistent pvacc)
#pragma unroll
        for (int kc = 0; kc < 4; kc++) {
            wmma::fragment<wmma::matrix_a,16,16,16,__half,wmma::row_major> a;
            wmma::load_matrix_sync(a, &Ps[(wid*16)*AQ_LD + kc*16], AQ_LD);
#pragma unroll
            for (int ni = 0; ni < 4; ni++) {
                wmma::fragment<wmma::matrix_b,16,16,16,__half,wmma::row_major> bf;
                wmma::load_matrix_sync(bf, &Vs[(kc*16)*AQ_LD + ni*16], AQ_LD);
                wmma::mma_sync(pvacc[ni], a, bf, pvacc[ni]);
            }
        }
        __syncthreads();   // protect K/V/P/S before next tile overwrites
    }

    // final: stage O in Ss, normalize per row, write half ctx
#pragma unroll
    for (int ni = 0; ni < 4; ni++)
        wmma::store_matrix_sync(&Ss[(wid*16)*AS_LD + ni*16], pvacc[ni], AS_LD, wmma::mem_row_major);
    __syncthreads();

    {
        float l = lrun + __shfl_xor_sync(0xffffffffu, lrun, 1);
        float inv = 1.f / l;
        size_t base = (size_t)((q0 + s_r)*BATCH + b) * DMODEL + col0 + s_c0;
#pragma unroll
        for (int u = 0; u < 4; u++) {
            float4 v0 = *(float4*)&Ss[s_r*AS_LD + s_c0 + u*8];
            float4 v1 = *(float4*)&Ss[s_r*AS_LD + s_c0 + u*8 + 4];
            __half2 h0 = __floats2half2_rn(v0.x*inv, v0.y*inv);
            __half2 h1 = __floats2half2_rn(v0.z*inv, v0.w*inv);
            __half2 h2 = __floats2half2_rn(v1.x*inv, v1.y*inv);
            __half2 h3 = __floats2half2_rn(v1.z*inv, v1.w*inv);
            uint4 u4; u4.x = *(uint32_t*)&h0; u4.y = *(uint32_t*)&h1;
            u4.z = *(uint32_t*)&h2; u4.w = *(uint32_t*)&h3;
            *(uint4*)&g_ctx[base + u*8] = u4;
        }
    }
}

// ---------------------------------------------------------------------------
extern "C" void kernel_launch(void* const* d_in, const int* in_sizes, int n_in,
                              void* d_out, int out_size)
{
    const float* query = (const float*)d_in[0];
    const float* key   = (const float*)d_in[1];
    const float* value = (const float*)d_in[2];
    const float* Wq    = (const float*)d_in[3];
    const float* bq    = (const float*)d_in[4];
    const float* Wk    = (const float*)d_in[5];
    const float* bk    = (const float*)d_in[6];
    const float* Wv    = (const float*)d_in[7];
    const float* bv    = (const float*)d_in[8];
    const float* Wo    = (const float*)d_in[9];
    const float* bo    = (const float*)d_in[10];
    const float* rel   = (const float*)d_in[11];
    float* out = (float*)d_out;

    void *pQ, *pK, *pV, *pC;
    cudaGetSymbolAddress(&pQ, g_Q);
    cudaGetSymbolAddress(&pK, g_K);
    cudaGetSymbolAddress(&pV, g_V);
    cudaGetSymbolAddress(&pC, g_ctx);

    cudaFuncSetAttribute(attn_kernel, cudaFuncAttributeMaxDynamicSharedMemorySize, ATTN_SMEM);

    dim3 gg(DMODEL / 128, MROWS / 128);   // (8, 32)
    dim3 bb(256);

    gemm_f16<1,0><<<gg, bb>>>(query, Wq, bq, pQ);
    gemm_f16<1,0><<<gg, bb>>>(key,   Wk, bk, pK);
    gemm_f16<1,0><<<gg, bb>>>(value, Wv, bv, pV);

    attn_kernel<<<dim3(SLEN/128, BATCH*HEADS), 256, ATTN_SMEM>>>(rel);

    gemm_f16<0,1><<<gg, bb>>>(pC, Wo, bo, out);
}

// round 6
// speedup vs baseline: 3.9260x; 1.4101x over previous
#include <cuda_runtime.h>
#include <cuda_fp16.h>
#include <mma.h>
#include <cstdint>
using namespace nvcuda;

#define SLEN    2048
#define BATCH   2
#define DMODEL  1024
#define HEADS   16
#define DK      64
#define MROWS   (SLEN*BATCH)          // 4096
#define NREL    (2*2048 - 1)          // 4095
#define SCALE_F 0.125f                // 1/sqrt(64)
#define EXP_OFF 12.0f                 // fixed softmax offset (cancels in normalization)

// Scratch (no device allocation allowed -> __device__ globals). fp16, layout
// [m = s*BATCH + b][n = h*64 + d]
__device__ __half g_Q[MROWS*DMODEL];
__device__ __half g_K[MROWS*DMODEL];
__device__ __half g_V[MROWS*DMODEL];
__device__ __half g_ctx[MROWS*DMODEL];

__device__ __forceinline__ uint32_t smem_u32(const void* p) {
    uint32_t a;
    asm("{ .reg .u64 t; cvta.to.shared.u64 t, %1; cvt.u32.u64 %0, t; }" : "=r"(a) : "l"(p));
    return a;
}

#define LDSM_X4(r0,r1,r2,r3,addr) \
    asm volatile("ldmatrix.sync.aligned.m8n8.x4.shared.b16 {%0,%1,%2,%3}, [%4];" \
        : "=r"(r0),"=r"(r1),"=r"(r2),"=r"(r3) : "r"(addr))
#define LDSM_X4_T(r0,r1,r2,r3,addr) \
    asm volatile("ldmatrix.sync.aligned.m8n8.x4.trans.shared.b16 {%0,%1,%2,%3}, [%4];" \
        : "=r"(r0),"=r"(r1),"=r"(r2),"=r"(r3) : "r"(addr))
#define MMA16816(d, a, b0, b1) \
    asm volatile("mma.sync.aligned.m16n8k16.row.col.f32.f16.f16.f32 " \
        "{%0,%1,%2,%3},{%4,%5,%6,%7},{%8,%9},{%0,%1,%2,%3};" \
        : "+f"((d)[0]),"+f"((d)[1]),"+f"((d)[2]),"+f"((d)[3]) \
        : "r"((a)[0]),"r"((a)[1]),"r"((a)[2]),"r"((a)[3]),"r"(b0),"r"(b1))
#define CP_ASYNC16(dst, src) \
    asm volatile("cp.async.cg.shared.global [%0], [%1], 16;" :: "r"(dst), "l"(src))
#define CP_COMMIT() asm volatile("cp.async.commit_group;" ::: "memory")
#define CP_WAIT(n)  asm volatile("cp.async.wait_group %0;" :: "n"(n) : "memory")

// ===========================================================================
// fp16 WMMA GEMM (unchanged from R4): out[m][n] = sum_k X[m][k]*W[n][k] + b[n]
// ===========================================================================
#define GLD 40

template<int OUT_HALF, int SRC_HALF>
__global__ __launch_bounds__(256)
void gemm_f16(const void* __restrict__ Xv, const float* __restrict__ W,
              const float* __restrict__ bias, void* __restrict__ outv)
{
    __shared__ __align__(16) char smraw[8*16*68*4];
    __half* Xs = (__half*)smraw;
    __half* Ws = (__half*)(smraw + 128*GLD*2);
    float*  patch = (float*)smraw;

    const int tid  = threadIdx.x;
    const int wid  = tid >> 5, lane = tid & 31;
    const int wm   = wid >> 1;
    const int wn   = wid & 1;
    const int m0   = blockIdx.y * 128;
    const int n0   = blockIdx.x * 128;

    const float*  Xf = (const float*)Xv;
    const __half* Xh = (const __half*)Xv;

    wmma::fragment<wmma::accumulator,16,16,16,float> acc[2][4];
#pragma unroll
    for (int mi = 0; mi < 2; mi++)
#pragma unroll
        for (int ni = 0; ni < 4; ni++) wmma::fill_fragment(acc[mi][ni], 0.f);

    const int row = tid >> 1;
    const int u0  = (tid & 1) * 4;
    const int uh0 = (tid & 1) * 2;

    float4 px[4], pw[4];
    uint4  hx[2];

    auto prefetch = [&](int it) {
        if (SRC_HALF) {
#pragma unroll
            for (int c = 0; c < 2; c++)
                hx[c] = *(const uint4*)&Xh[(size_t)(m0 + row) * DMODEL + it*32 + (uh0 + c)*8];
        } else {
#pragma unroll
            for (int c = 0; c < 4; c++)
                px[c] = *(const float4*)&Xf[(size_t)(m0 + row) * DMODEL + it*32 + (u0 + c)*4];
        }
#pragma unroll
        for (int c = 0; c < 4; c++)
            pw[c] = *(const float4*)&W[(size_t)(n0 + row) * DMODEL + it*32 + (u0 + c)*4];
    };

    prefetch(0);
    const int NIT = DMODEL / 32;
    for (int it = 0; it < NIT; it++) {
        __syncthreads();
        if (SRC_HALF) {
#pragma unroll
            for (int c = 0; c < 2; c++)
                *(uint4*)&Xs[row*GLD + (uh0 + c)*8] = hx[c];
        } else {
#pragma unroll
            for (int c = 0; c < 4; c++) {
                __half2 a = __floats2half2_rn(px[c].x, px[c].y);
                __half2 b = __floats2half2_rn(px[c].z, px[c].w);
                *(__half2*)&Xs[row*GLD + (u0 + c)*4]     = a;
                *(__half2*)&Xs[row*GLD + (u0 + c)*4 + 2] = b;
            }
        }
#pragma unroll
        for (int c = 0; c < 4; c++) {
            __half2 a = __floats2half2_rn(pw[c].x, pw[c].y);
            __half2 b = __floats2half2_rn(pw[c].z, pw[c].w);
            *(__half2*)&Ws[row*GLD + (u0 + c)*4]     = a;
            *(__half2*)&Ws[row*GLD + (u0 + c)*4 + 2] = b;
        }
        __syncthreads();
        if (it + 1 < NIT) prefetch(it + 1);

#pragma unroll
        for (int ks = 0; ks < 2; ks++) {
            wmma::fragment<wmma::matrix_a,16,16,16,__half,wmma::row_major> a[2];
            wmma::fragment<wmma::matrix_b,16,16,16,__half,wmma::col_major> bf[4];
#pragma unroll
            for (int mi = 0; mi < 2; mi++)
                wmma::load_matrix_sync(a[mi], &Xs[(wm*32 + mi*16)*GLD + ks*16], GLD);
#pragma unroll
            for (int ni = 0; ni < 4; ni++)
                wmma::load_matrix_sync(bf[ni], &Ws[(wn*64 + ni*16)*GLD + ks*16], GLD);
#pragma unroll
            for (int mi = 0; mi < 2; mi++)
#pragma unroll
                for (int ni = 0; ni < 4; ni++)
                    wmma::mma_sync(acc[mi][ni], a[mi], bf[ni], acc[mi][ni]);
        }
    }
    __syncthreads();

    float* pp = patch + wid * 16 * 68;
#pragma unroll
    for (int mi = 0; mi < 2; mi++) {
#pragma unroll
        for (int ni = 0; ni < 4; ni++)
            wmma::store_matrix_sync(pp + ni*16, acc[mi][ni], 68, wmma::mem_row_major);
        __syncwarp();
#pragma unroll
        for (int l = 0; l < 8; l++) {
            int f = lane + l * 32;
            int r = f >> 4, c4 = f & 15;
            int m = m0 + wm*32 + mi*16 + r;
            int n = n0 + wn*64 + c4*4;
            float4 v = *(float4*)&pp[r*68 + c4*4];
            float4 bb = *(const float4*)&bias[n];
            v.x += bb.x; v.y += bb.y; v.z += bb.z; v.w += bb.w;
            if (OUT_HALF) {
                __half2 h0 = __floats2half2_rn(v.x, v.y);
                __half2 h1 = __floats2half2_rn(v.z, v.w);
                uint2 u; u.x = *(uint32_t*)&h0; u.y = *(uint32_t*)&h1;
                *(uint2*)&((__half*)outv)[(size_t)m * DMODEL + n] = u;
            } else {
                *(float4*)&((float*)outv)[(size_t)m * DMODEL + n] = v;
            }
        }
        __syncwarp();
    }
}

// ===========================================================================
// Flash attention v2: raw mma.m16n8k16, register softmax, register P,
// cp.async double-buffered K/V, preloaded bias window.
// Grid (16 q-tiles of 128, 32 bh). Block 256 (8 warps x 16 q-rows).
// Smem: sball f32[2176] + kv[2 stages][K 64x72 | V 64x72] = 45568B static.
// ===========================================================================
#define KV_STG 18432          // bytes per stage (K 9216 + V 9216)
#define NTILES (SLEN/64)      // 32

__global__ __launch_bounds__(256, 2)
void attn_kernel(const float* __restrict__ rel_table)
{
    __shared__ __align__(16) float  sball[2176];
    __shared__ __align__(16) __half kvbuf[2 * KV_STG / 2];

    const int tid  = threadIdx.x;
    const int wid  = tid >> 5, lane = tid & 31;
    const int q0   = blockIdx.x * 128;
    const int bh   = blockIdx.y;
    const int h    = bh & (HEADS - 1);
    const int b    = bh >> 4;
    const int col0 = h * DK;

    const uint32_t kvu = smem_u32(kvbuf);

    // ---- bias window preload: sball[d] = table[clip(q0 + d)][h]
    // (lookup uses d = row_local - k_global + 2047, so table idx = q0 + d)
    for (int i = tid; i < 2176; i += 256) {
        int idx = q0 + i;                      // FIX (was q0 + i - 2047)
        idx = min(max(idx, 0), NREL - 1);
        sball[i] = __ldg(&rel_table[idx * HEADS + h]);
    }

    // ---- stage Q (128 rows x 64 halves) into stage-0 area, then ldmatrix
#pragma unroll
    for (int c = 0; c < 4; c++) {
        int idx = tid + c * 256;            // 0..1023
        int r = idx >> 3, c16 = idx & 7;
        *(uint4*)((char*)kvbuf + r*144 + c16*16) =
            *(const uint4*)&g_Q[(size_t)((q0 + r)*BATCH + b) * DMODEL + col0 + c16*8];
    }
    __syncthreads();

    uint32_t Qa[4][4];
    {
        int rsel = lane & 15, csel = (lane >> 4) & 1;
#pragma unroll
        for (int kc = 0; kc < 4; kc++) {
            uint32_t addr = kvu + (wid*16 + rsel)*144 + kc*32 + csel*16;
            LDSM_X4(Qa[kc][0], Qa[kc][1], Qa[kc][2], Qa[kc][3], addr);
        }
    }
    __syncthreads();   // Q reads done; stage 0 free for prefetch

    // ---- cp.async prefetch helper (K + V tile -> stage)
    auto prefetch = [&](int t, int stg) {
        int k0 = t * 64;
#pragma unroll
        for (int c = 0; c < 4; c++) {
            int idx = tid + c * 256;          // 0..1023
            int isv = idx >> 9;               // 0:K 1:V
            int r   = (idx >> 3) & 63;
            int c16 = idx & 7;
            const __half* src = (isv ? g_V : g_K)
                + (size_t)((k0 + r)*BATCH + b) * DMODEL + col0 + c16*8;
            uint32_t dst = kvu + stg*KV_STG + isv*9216 + r*144 + c16*16;
            CP_ASYNC16(dst, src);
        }
    };

    prefetch(0, 0);
    CP_COMMIT();

    const int g  = lane >> 2, tg = lane & 3;
    const int row0 = wid*16 + g;

    float Oacc[8][4];
#pragma unroll
    for (int nt = 0; nt < 8; nt++)
#pragma unroll
        for (int e = 0; e < 4; e++) Oacc[nt][e] = 0.f;
    float lrun0 = 0.f, lrun1 = 0.f;

    for (int t = 0; t < NTILES; t++) {
        const int st = t & 1;
        if (t + 1 < NTILES) { prefetch(t + 1, (t + 1) & 1); CP_COMMIT(); CP_WAIT(1); }
        else                { CP_WAIT(0); }
        __syncthreads();

        const uint32_t kb = kvu + st*KV_STG;
        const uint32_t vb = kb + 9216;
        const int lr  = lane & 7;
        const int sel = lane >> 3;            // 0..3

        // ---- S = Q K^T  (16 q-rows x 64 k-cols per warp)
        float sacc[8][4];
#pragma unroll
        for (int nt = 0; nt < 8; nt++)
#pragma unroll
            for (int e = 0; e < 4; e++) sacc[nt][e] = 0.f;

#pragma unroll
        for (int kc = 0; kc < 4; kc++) {
#pragma unroll
            for (int tp = 0; tp < 4; tp++) {
                uint32_t b0, b1, b2, b3;
                uint32_t addr = kb + ((tp*2 + (sel >> 1))*8 + lr)*144
                              + kc*32 + (sel & 1)*16;
                LDSM_X4(b0, b1, b2, b3, addr);
                MMA16816(sacc[tp*2],     Qa[kc], b0, b1);
                MMA16816(sacc[tp*2 + 1], Qa[kc], b2, b3);
            }
        }

        // ---- softmax (fixed offset) + P as A-fragments, all in registers
        const int dconst = 2047 - t*64;
        uint32_t Pa[4][4];
#pragma unroll
        for (int nt = 0; nt < 8; nt++) {
            int colL = nt*8 + 2*tg;
            int d00  = row0 - colL + dconst;
            float v0 = fmaf(sacc[nt][0], SCALE_F, sball[d00])     - EXP_OFF;
            float v1 = fmaf(sacc[nt][1], SCALE_F, sball[d00 - 1]) - EXP_OFF;
            float v2 = fmaf(sacc[nt][2], SCALE_F, sball[d00 + 8]) - EXP_OFF;
            float v3 = fmaf(sacc[nt][3], SCALE_F, sball[d00 + 7]) - EXP_OFF;
            __half2 h01 = __floats2half2_rn(__expf(v0), __expf(v1));
            __half2 h23 = __floats2half2_rn(__expf(v2), __expf(v3));
            float2 f01 = __half22float2(h01);
            float2 f23 = __half22float2(h23);
            lrun0 += f01.x + f01.y;
            lrun1 += f23.x + f23.y;
            Pa[nt >> 1][(nt & 1)*2 + 0] = *(uint32_t*)&h01;
            Pa[nt >> 1][(nt & 1)*2 + 1] = *(uint32_t*)&h23;
        }

        // ---- O += P V
#pragma unroll
        for (int kc = 0; kc < 4; kc++) {
#pragma unroll
            for (int tp = 0; tp < 4; tp++) {
                uint32_t b0, b1, b2, b3;
                uint32_t addr = vb + (kc*16 + (sel & 1)*8 + lr)*144
                              + (tp*2 + (sel >> 1))*16;
                LDSM_X4_T(b0, b1, b2, b3, addr);
                MMA16816(Oacc[tp*2],     Pa[kc], b0, b1);
                MMA16816(Oacc[tp*2 + 1], Pa[kc], b2, b3);
            }
        }
        __syncthreads();   // all ldsm reads of this stage done before overwrite
    }

    // ---- normalize & write
    lrun0 += __shfl_xor_sync(0xffffffffu, lrun0, 1);
    lrun0 += __shfl_xor_sync(0xffffffffu, lrun0, 2);
    lrun1 += __shfl_xor_sync(0xffffffffu, lrun1, 1);
    lrun1 += __shfl_xor_sync(0xffffffffu, lrun1, 2);
    const float inv0 = 1.f / lrun0;
    const float inv1 = 1.f / lrun1;

#pragma unroll
    for (int nt = 0; nt < 8; nt++) {
        __half2 h0 = __floats2half2_rn(Oacc[nt][0]*inv0, Oacc[nt][1]*inv0);
        __half2 h1 = __floats2half2_rn(Oacc[nt][2]*inv1, Oacc[nt][3]*inv1);
        size_t base = (size_t)((q0 + row0)*BATCH + b) * DMODEL + col0 + nt*8 + 2*tg;
        *(uint32_t*)&g_ctx[base] = *(uint32_t*)&h0;
        *(uint32_t*)&g_ctx[base + 8*BATCH*DMODEL] = *(uint32_t*)&h1;
    }
}

// ---------------------------------------------------------------------------
extern "C" void kernel_launch(void* const* d_in, const int* in_sizes, int n_in,
                              void* d_out, int out_size)
{
    const float* query = (const float*)d_in[0];
    const float* key   = (const float*)d_in[1];
    const float* value = (const float*)d_in[2];
    const float* Wq    = (const float*)d_in[3];
    const float* bq    = (const float*)d_in[4];
    const float* Wk    = (const float*)d_in[5];
    const float* bk    = (const float*)d_in[6];
    const float* Wv    = (const float*)d_in[7];
    const float* bv    = (const float*)d_in[8];
    const float* Wo    = (const float*)d_in[9];
    const float* bo    = (const float*)d_in[10];
    const float* rel   = (const float*)d_in[11];
    float* out = (float*)d_out;

    void *pQ, *pK, *pV, *pC;
    cudaGetSymbolAddress(&pQ, g_Q);
    cudaGetSymbolAddress(&pK, g_K);
    cudaGetSymbolAddress(&pV, g_V);
    cudaGetSymbolAddress(&pC, g_ctx);

    dim3 gg(DMODEL / 128, MROWS / 128);   // (8, 32)
    dim3 bb(256);

    gemm_f16<1,0><<<gg, bb>>>(query, Wq, bq, pQ);
    gemm_f16<1,0><<<gg, bb>>>(key,   Wk, bk, pK);
    gemm_f16<1,0><<<gg, bb>>>(value, Wv, bv, pV);

    attn_kernel<<<dim3(SLEN/128, BATCH*HEADS), 256>>>(rel);

    gemm_f16<0,1><<<gg, bb>>>(pC, Wo, bo, out);
}

// round 8
// speedup vs baseline: 6.2800x; 1.5996x over previous
#include <cuda_runtime.h>
#include <cuda_fp16.h>
#include <mma.h>
#include <cstdint>
using namespace nvcuda;

#define SLEN    2048
#define BATCH   2
#define DMODEL  1024
#define HEADS   16
#define DK      64
#define MROWS   (SLEN*BATCH)          // 4096
#define NREL    (2*2048 - 1)          // 4095
#define SCALE_F 0.125f                // 1/sqrt(64)
#define EXP_OFF 12.0f                 // fixed softmax offset (cancels in normalization)

// Scratch (no device allocation allowed -> __device__ globals). fp16.
__device__ __half g_Q[MROWS*DMODEL];          // projected Q  [m][h*64+d]
__device__ __half g_K[MROWS*DMODEL];
__device__ __half g_V[MROWS*DMODEL];
__device__ __half g_ctx[MROWS*DMODEL];
__device__ __half g_xq[MROWS*DMODEL];         // half-converted inputs
__device__ __half g_xk[MROWS*DMODEL];
__device__ __half g_xv[MROWS*DMODEL];
__device__ __half g_wq[DMODEL*DMODEL];        // half-converted weights
__device__ __half g_wk[DMODEL*DMODEL];
__device__ __half g_wv[DMODEL*DMODEL];
__device__ __half g_wo[DMODEL*DMODEL];

__device__ __forceinline__ uint32_t smem_u32(const void* p) {
    uint32_t a;
    asm("{ .reg .u64 t; cvta.to.shared.u64 t, %1; cvt.u32.u64 %0, t; }" : "=r"(a) : "l"(p));
    return a;
}

#define LDSM_X4(r0,r1,r2,r3,addr) \
    asm volatile("ldmatrix.sync.aligned.m8n8.x4.shared.b16 {%0,%1,%2,%3}, [%4];" \
        : "=r"(r0),"=r"(r1),"=r"(r2),"=r"(r3) : "r"(addr))
#define LDSM_X4_T(r0,r1,r2,r3,addr) \
    asm volatile("ldmatrix.sync.aligned.m8n8.x4.trans.shared.b16 {%0,%1,%2,%3}, [%4];" \
        : "=r"(r0),"=r"(r1),"=r"(r2),"=r"(r3) : "r"(addr))
#define MMA16816(d, a, b0, b1) \
    asm volatile("mma.sync.aligned.m16n8k16.row.col.f32.f16.f16.f32 " \
        "{%0,%1,%2,%3},{%4,%5,%6,%7},{%8,%9},{%0,%1,%2,%3};" \
        : "+f"((d)[0]),"+f"((d)[1]),"+f"((d)[2]),"+f"((d)[3]) \
        : "r"((a)[0]),"r"((a)[1]),"r"((a)[2]),"r"((a)[3]),"r"(b0),"r"(b1))
#define CP_ASYNC16(dst, src) \
    asm volatile("cp.async.cg.shared.global [%0], [%1], 16;" :: "r"(dst), "l"(src))
#define CP_COMMIT() asm volatile("cp.async.commit_group;" ::: "memory")
#define CP_WAIT(n)  asm volatile("cp.async.wait_group %0;" :: "n"(n) : "memory")

// ===========================================================================
// f32 -> f16 conversion (8 elems/thread, vectorized)
// ===========================================================================
__global__ __launch_bounds__(256)
void cvt_f2h(const float* __restrict__ s, __half* __restrict__ d, int n)
{
    int i = (blockIdx.x * 256 + threadIdx.x) * 8;
    if (i < n) {
        float4 a = *(const float4*)&s[i];
        float4 b = *(const float4*)&s[i + 4];
        __half2 h0 = __floats2half2_rn(a.x, a.y);
        __half2 h1 = __floats2half2_rn(a.z, a.w);
        __half2 h2 = __floats2half2_rn(b.x, b.y);
        __half2 h3 = __floats2half2_rn(b.z, b.w);
        uint4 u;
        u.x = *(uint32_t*)&h0; u.y = *(uint32_t*)&h1;
        u.z = *(uint32_t*)&h2; u.w = *(uint32_t*)&h3;
        *(uint4*)&d[i] = u;
    }
}

// ===========================================================================
// All-half cp.async pipelined GEMM body: out[m][n] = sum_k X[m][k]*W[n][k]+b[n]
// Tile 128x128xBK32, 3-stage cp.async, 256 thr (8 warps), warp tile 32x64.
// Stage layout: X tile [128][40]h (10240B, 64B data + 16B pad/row) | W same.
// ===========================================================================
#define BK     32
#define PSTG   3
#define XS_LD  40
#define STG_B  20480
#define GEMM_DSMEM (PSTG*STG_B)      // 61440

__device__ __forceinline__ void gemm_body(
    char* sm, const __half* __restrict__ X, const __half* __restrict__ W,
    const float* __restrict__ bias, void* __restrict__ outv, int out_half,
    int m0, int n0)
{
    const uint32_t smu = smem_u32(sm);
    const int tid = threadIdx.x;
    const int wid = tid >> 5, lane = tid & 31;
    const int wm = wid >> 1, wn = wid & 1;

    wmma::fragment<wmma::accumulator,16,16,16,float> acc[2][4];
#pragma unroll
    for (int mi = 0; mi < 2; mi++)
#pragma unroll
        for (int ni = 0; ni < 4; ni++) wmma::fill_fragment(acc[mi][ni], 0.f);

    // per-thread loader: 1024 chunks of 16B per stage (X 512 + W 512),
    // 4 chunks/thread: idx = tid + c*256
    auto issue = [&](int it) {
        const int kb = it * BK;
        const int slot = it % PSTG;
#pragma unroll
        for (int c = 0; c < 4; c++) {
            int idx = tid + c * 256;       // 0..1023
            int isw = idx >> 9;            // 0:X 1:W
            int r   = (idx >> 2) & 127;
            int ch  = idx & 3;
            const __half* src = (isw ? W : X)
                + (size_t)((isw ? n0 : m0) + r) * DMODEL + kb + ch * 8;
            uint32_t dst = smu + slot * STG_B + isw * 10240 + r * 80 + ch * 16;
            CP_ASYNC16(dst, src);
        }
        CP_COMMIT();
    };

    issue(0); issue(1);
    const int NIT = DMODEL / BK;           // 32
    for (int it = 0; it < NIT; it++) {
        if (it < NIT - 1) CP_WAIT(1); else CP_WAIT(0);
        __syncthreads();
        if (it + 2 < NIT) issue(it + 2);   // safe: all warps done with slot (it-1)

        __half* Xs = (__half*)(sm + (it % PSTG) * STG_B);
        __half* Ws = (__half*)(sm + (it % PSTG) * STG_B + 10240);
#pragma unroll
        for (int ks = 0; ks < 2; ks++) {
            wmma::fragment<wmma::matrix_a,16,16,16,__half,wmma::row_major> a[2];
            wmma::fragment<wmma::matrix_b,16,16,16,__half,wmma::col_major> bf[4];
#pragma unroll
            for (int mi = 0; mi < 2; mi++)
                wmma::load_matrix_sync(a[mi], &Xs[(wm*32 + mi*16)*XS_LD + ks*16], XS_LD);
#pragma unroll
            for (int ni = 0; ni < 4; ni++)
                wmma::load_matrix_sync(bf[ni], &Ws[(wn*64 + ni*16)*XS_LD + ks*16], XS_LD);
#pragma unroll
            for (int mi = 0; mi < 2; mi++)
#pragma unroll
                for (int ni = 0; ni < 4; ni++)
                    wmma::mma_sync(acc[mi][ni], a[mi], bf[ni], acc[mi][ni]);
        }
    }
    __syncthreads();   // pipeline buffers dead; reuse as epilogue patches

    float* pp = (float*)sm + wid * 16 * 68;
#pragma unroll
    for (int mi = 0; mi < 2; mi++) {
#pragma unroll
        for (int ni = 0; ni < 4; ni++)
            wmma::store_matrix_sync(pp + ni*16, acc[mi][ni], 68, wmma::mem_row_major);
        __syncwarp();
#pragma unroll
        for (int l = 0; l < 8; l++) {
            int f = lane + l * 32;
            int r = f >> 4, c4 = f & 15;
            int m = m0 + wm*32 + mi*16 + r;
            int n = n0 + wn*64 + c4*4;
            float4 v = *(float4*)&pp[r*68 + c4*4];
            float4 bb = *(const float4*)&bias[n];
            v.x += bb.x; v.y += bb.y; v.z += bb.z; v.w += bb.w;
            if (out_half) {
                __half2 h0 = __floats2half2_rn(v.x, v.y);
                __half2 h1 = __floats2half2_rn(v.z, v.w);
                uint2 u; u.x = *(uint32_t*)&h0; u.y = *(uint32_t*)&h1;
                *(uint2*)&((__half*)outv)[(size_t)m * DMODEL + n] = u;
            } else {
                *(float4*)&((float*)outv)[(size_t)m * DMODEL + n] = v;
            }
        }
        __syncwarp();
    }
}

// fused Q/K/V projection: grid (8, 32, 3)
__global__ __launch_bounds__(256, 2)
void gemm_qkv(const float* __restrict__ bq, const float* __restrict__ bk,
              const float* __restrict__ bv)
{
    extern __shared__ __align__(16) char sm[];
    const int z = blockIdx.z;
    const __half* X = (z == 0) ? g_xq : (z == 1) ? g_xk : g_xv;
    const __half* W = (z == 0) ? g_wq : (z == 1) ? g_wk : g_wv;
    const float*  B = (z == 0) ? bq   : (z == 1) ? bk   : bv;
    __half* O      = (z == 0) ? g_Q  : (z == 1) ? g_K  : g_V;
    gemm_body(sm, X, W, B, O, 1, blockIdx.y * 128, blockIdx.x * 128);
}

// output projection: ctx(half) @ Wo^T + bo -> f32 out
__global__ __launch_bounds__(256, 2)
void gemm_out(const float* __restrict__ bo, float* __restrict__ out)
{
    extern __shared__ __align__(16) char sm[];
    gemm_body(sm, g_ctx, g_wo, bo, out, 0, blockIdx.y * 128, blockIdx.x * 128);
}

// ===========================================================================
// Flash attention (unchanged from R6): raw mma.m16n8k16, register softmax,
// register P, cp.async double-buffered K/V, preloaded bias window.
// ===========================================================================
#define KV_STG 18432
#define NTILES (SLEN/64)

__global__ __launch_bounds__(256, 2)
void attn_kernel(const float* __restrict__ rel_table)
{
    __shared__ __align__(16) float  sball[2176];
    __shared__ __align__(16) __half kvbuf[2 * KV_STG / 2];

    const int tid  = threadIdx.x;
    const int wid  = tid >> 5, lane = tid & 31;
    const int q0   = blockIdx.x * 128;
    const int bh   = blockIdx.y;
    const int h    = bh & (HEADS - 1);
    const int b    = bh >> 4;
    const int col0 = h * DK;

    const uint32_t kvu = smem_u32(kvbuf);

    for (int i = tid; i < 2176; i += 256) {
        int idx = q0 + i;
        idx = min(max(idx, 0), NREL - 1);
        sball[i] = __ldg(&rel_table[idx * HEADS + h]);
    }

#pragma unroll
    for (int c = 0; c < 4; c++) {
        int idx = tid + c * 256;
        int r = idx >> 3, c16 = idx & 7;
        *(uint4*)((char*)kvbuf + r*144 + c16*16) =
            *(const uint4*)&g_Q[(size_t)((q0 + r)*BATCH + b) * DMODEL + col0 + c16*8];
    }
    __syncthreads();

    uint32_t Qa[4][4];
    {
        int rsel = lane & 15, csel = (lane >> 4) & 1;
#pragma unroll
        for (int kc = 0; kc < 4; kc++) {
            uint32_t addr = kvu + (wid*16 + rsel)*144 + kc*32 + csel*16;
            LDSM_X4(Qa[kc][0], Qa[kc][1], Qa[kc][2], Qa[kc][3], addr);
        }
    }
    __syncthreads();

    auto prefetch = [&](int t, int stg) {
        int k0 = t * 64;
#pragma unroll
        for (int c = 0; c < 4; c++) {
            int idx = tid + c * 256;
            int isv = idx >> 9;
            int r   = (idx >> 3) & 63;
            int c16 = idx & 7;
            const __half* src = (isv ? g_V : g_K)
                + (size_t)((k0 + r)*BATCH + b) * DMODEL + col0 + c16*8;
            uint32_t dst = kvu + stg*KV_STG + isv*9216 + r*144 + c16*16;
            CP_ASYNC16(dst, src);
        }
    };

    prefetch(0, 0);
    CP_COMMIT();

    const int g  = lane >> 2, tg = lane & 3;
    const int row0 = wid*16 + g;

    float Oacc[8][4];
#pragma unroll
    for (int nt = 0; nt < 8; nt++)
#pragma unroll
        for (int e = 0; e < 4; e++) Oacc[nt][e] = 0.f;
    float lrun0 = 0.f, lrun1 = 0.f;

    for (int t = 0; t < NTILES; t++) {
        const int st = t & 1;
        if (t + 1 < NTILES) { prefetch(t + 1, (t + 1) & 1); CP_COMMIT(); CP_WAIT(1); }
        else                { CP_WAIT(0); }
        __syncthreads();

        const uint32_t kb = kvu + st*KV_STG;
        const uint32_t vb = kb + 9216;
        const int lr  = lane & 7;
        const int sel = lane >> 3;

        float sacc[8][4];
#pragma unroll
        for (int nt = 0; nt < 8; nt++)
#pragma unroll
            for (int e = 0; e < 4; e++) sacc[nt][e] = 0.f;

#pragma unroll
        for (int kc = 0; kc < 4; kc++) {
#pragma unroll
            for (int tp = 0; tp < 4; tp++) {
                uint32_t b0, b1, b2, b3;
                uint32_t addr = kb + ((tp*2 + (sel >> 1))*8 + lr)*144
                              + kc*32 + (sel & 1)*16;
                LDSM_X4(b0, b1, b2, b3, addr);
                MMA16816(sacc[tp*2],     Qa[kc], b0, b1);
                MMA16816(sacc[tp*2 + 1], Qa[kc], b2, b3);
            }
        }

        const int dconst = 2047 - t*64;
        uint32_t Pa[4][4];
#pragma unroll
        for (int nt = 0; nt < 8; nt++) {
            int colL = nt*8 + 2*tg;
            int d00  = row0 - colL + dconst;
            float v0 = fmaf(sacc[nt][0], SCALE_F, sball[d00])     - EXP_OFF;
            float v1 = fmaf(sacc[nt][1], SCALE_F, sball[d00 - 1]) - EXP_OFF;
            float v2 = fmaf(sacc[nt][2], SCALE_F, sball[d00 + 8]) - EXP_OFF;
            float v3 = fmaf(sacc[nt][3], SCALE_F, sball[d00 + 7]) - EXP_OFF;
            __half2 h01 = __floats2half2_rn(__expf(v0), __expf(v1));
            __half2 h23 = __floats2half2_rn(__expf(v2), __expf(v3));
            float2 f01 = __half22float2(h01);
            float2 f23 = __half22float2(h23);
            lrun0 += f01.x + f01.y;
            lrun1 += f23.x + f23.y;
            Pa[nt >> 1][(nt & 1)*2 + 0] = *(uint32_t*)&h01;
            Pa[nt >> 1][(nt & 1)*2 + 1] = *(uint32_t*)&h23;
        }

#pragma unroll
        for (int kc = 0; kc < 4; kc++) {
#pragma unroll
            for (int tp = 0; tp < 4; tp++) {
                uint32_t b0, b1, b2, b3;
                uint32_t addr = vb + (kc*16 + (sel & 1)*8 + lr)*144
                              + (tp*2 + (sel >> 1))*16;
                LDSM_X4_T(b0, b1, b2, b3, addr);
                MMA16816(Oacc[tp*2],     Pa[kc], b0, b1);
                MMA16816(Oacc[tp*2 + 1], Pa[kc], b2, b3);
            }
        }
        __syncthreads();
    }

    lrun0 += __shfl_xor_sync(0xffffffffu, lrun0, 1);
    lrun0 += __shfl_xor_sync(0xffffffffu, lrun0, 2);
    lrun1 += __shfl_xor_sync(0xffffffffu, lrun1, 1);
    lrun1 += __shfl_xor_sync(0xffffffffu, lrun1, 2);
    const float inv0 = 1.f / lrun0;
    const float inv1 = 1.f / lrun1;

#pragma unroll
    for (int nt = 0; nt < 8; nt++) {
        __half2 h0 = __floats2half2_rn(Oacc[nt][0]*inv0, Oacc[nt][1]*inv0);
        __half2 h1 = __floats2half2_rn(Oacc[nt][2]*inv1, Oacc[nt][3]*inv1);
        size_t base = (size_t)((q0 + row0)*BATCH + b) * DMODEL + col0 + nt*8 + 2*tg;
        *(uint32_t*)&g_ctx[base] = *(uint32_t*)&h0;
        *(uint32_t*)&g_ctx[base + 8*BATCH*DMODEL] = *(uint32_t*)&h1;
    }
}

// ---------------------------------------------------------------------------
extern "C" void kernel_launch(void* const* d_in, const int* in_sizes, int n_in,
                              void* d_out, int out_size)
{
    const float* query = (const float*)d_in[0];
    const float* key   = (const float*)d_in[1];
    const float* value = (const float*)d_in[2];
    const float* Wq    = (const float*)d_in[3];
    const float* bq    = (const float*)d_in[4];
    const float* Wk    = (const float*)d_in[5];
    const float* bk    = (const float*)d_in[6];
    const float* Wv    = (const float*)d_in[7];
    const float* bv    = (const float*)d_in[8];
    const float* Wo    = (const float*)d_in[9];
    const float* bo    = (const float*)d_in[10];
    const float* rel   = (const float*)d_in[11];
    float* out = (float*)d_out;

    void *pxq, *pxk, *pxv, *pwq, *pwk, *pwv, *pwo;
    cudaGetSymbolAddress(&pxq, g_xq);
    cudaGetSymbolAddress(&pxk, g_xk);
    cudaGetSymbolAddress(&pxv, g_xv);
    cudaGetSymbolAddress(&pwq, g_wq);
    cudaGetSymbolAddress(&pwk, g_wk);
    cudaGetSymbolAddress(&pwv, g_wv);
    cudaGetSymbolAddress(&pwo, g_wo);

    cudaFuncSetAttribute(gemm_qkv, cudaFuncAttributeMaxDynamicSharedMemorySize, GEMM_DSMEM);
    cudaFuncSetAttribute(gemm_out, cudaFuncAttributeMaxDynamicSharedMemorySize, GEMM_DSMEM);

    const int NIN = MROWS * DMODEL;      // 4M
    const int NW  = DMODEL * DMODEL;     // 1M

    cvt_f2h<<<NIN/8/256, 256>>>(query, (__half*)pxq, NIN);
    cvt_f2h<<<NIN/8/256, 256>>>(key,   (__half*)pxk, NIN);
    cvt_f2h<<<NIN/8/256, 256>>>(value, (__half*)pxv, NIN);
    cvt_f2h<<<NW/8/256,  256>>>(Wq,    (__half*)pwq, NW);
    cvt_f2h<<<NW/8/256,  256>>>(Wk,    (__half*)pwk, NW);
    cvt_f2h<<<NW/8/256,  256>>>(Wv,    (__half*)pwv, NW);
    cvt_f2h<<<NW/8/256,  256>>>(Wo,    (__half*)pwo, NW);

    gemm_qkv<<<dim3(DMODEL/128, MROWS/128, 3), 256, GEMM_DSMEM>>>(bq, bk, bv);

    attn_kernel<<<dim3(SLEN/128, BATCH*HEADS), 256>>>(rel);

    gemm_out<<<dim3(DMODEL/128, MROWS/128), 256, GEMM_DSMEM>>>(bo, out);
}

// round 10
// speedup vs baseline: 6.4839x; 1.0325x over previous
#include <cuda_runtime.h>
#include <cuda_fp16.h>
#include <mma.h>
#include <cstdint>
using namespace nvcuda;

#define SLEN    2048
#define BATCH   2
#define DMODEL  1024
#define HEADS   16
#define DK      64
#define MROWS   (SLEN*BATCH)          // 4096
#define NREL    (2*2048 - 1)          // 4095
#define SCALE_F 0.125f                // 1/sqrt(64)
#define EXP_OFF 12.0f                 // fixed softmax offset (cancels in normalization)

// Scratch (no device allocation allowed -> __device__ globals). fp16.
__device__ __half g_Q[MROWS*DMODEL];          // projected Q  [m][h*64+d]
__device__ __half g_K[MROWS*DMODEL];
__device__ __half g_V[MROWS*DMODEL];
__device__ __half g_ctx[MROWS*DMODEL];
__device__ __half g_xq[MROWS*DMODEL];         // half-converted inputs
__device__ __half g_xk[MROWS*DMODEL];
__device__ __half g_xv[MROWS*DMODEL];
__device__ __half g_wq[DMODEL*DMODEL];        // half-converted weights
__device__ __half g_wk[DMODEL*DMODEL];
__device__ __half g_wv[DMODEL*DMODEL];
__device__ __half g_wo[DMODEL*DMODEL];

__device__ __forceinline__ uint32_t smem_u32(const void* p) {
    uint32_t a;
    asm("{ .reg .u64 t; cvta.to.shared.u64 t, %1; cvt.u32.u64 %0, t; }" : "=r"(a) : "l"(p));
    return a;
}

#define LDSM_X4(r0,r1,r2,r3,addr) \
    asm volatile("ldmatrix.sync.aligned.m8n8.x4.shared.b16 {%0,%1,%2,%3}, [%4];" \
        : "=r"(r0),"=r"(r1),"=r"(r2),"=r"(r3) : "r"(addr))
#define LDSM_X4_T(r0,r1,r2,r3,addr) \
    asm volatile("ldmatrix.sync.aligned.m8n8.x4.trans.shared.b16 {%0,%1,%2,%3}, [%4];" \
        : "=r"(r0),"=r"(r1),"=r"(r2),"=r"(r3) : "r"(addr))
#define MMA16816(d, a, b0, b1) \
    asm volatile("mma.sync.aligned.m16n8k16.row.col.f32.f16.f16.f32 " \
        "{%0,%1,%2,%3},{%4,%5,%6,%7},{%8,%9},{%0,%1,%2,%3};" \
        : "+f"((d)[0]),"+f"((d)[1]),"+f"((d)[2]),"+f"((d)[3]) \
        : "r"((a)[0]),"r"((a)[1]),"r"((a)[2]),"r"((a)[3]),"r"(b0),"r"(b1))
#define CP_ASYNC16(dst, src) \
    asm volatile("cp.async.cg.shared.global [%0], [%1], 16;" :: "r"(dst), "l"(src))
#define CP_COMMIT() asm volatile("cp.async.commit_group;" ::: "memory")
#define CP_WAIT(n)  asm volatile("cp.async.wait_group %0;" :: "n"(n) : "memory")

// ===========================================================================
// f32 -> f16 conversion (8 elems/thread, vectorized)
// ===========================================================================
__global__ __launch_bounds__(256)
void cvt_f2h(const float* __restrict__ s, __half* __restrict__ d, int n)
{
    int i = (blockIdx.x * 256 + threadIdx.x) * 8;
    if (i < n) {
        float4 a = *(const float4*)&s[i];
        float4 b = *(const float4*)&s[i + 4];
        __half2 h0 = __floats2half2_rn(a.x, a.y);
        __half2 h1 = __floats2half2_rn(a.z, a.w);
        __half2 h2 = __floats2half2_rn(b.x, b.y);
        __half2 h3 = __floats2half2_rn(b.z, b.w);
        uint4 u;
        u.x = *(uint32_t*)&h0; u.y = *(uint32_t*)&h1;
        u.z = *(uint32_t*)&h2; u.w = *(uint32_t*)&h3;
        *(uint4*)&d[i] = u;
    }
}

// ===========================================================================
// All-half GEMM body: out[m][n] = sum_k X[m][k]*W[n][k] + b[n]
// Tile 128x128xBK64, 2-stage cp.async (1-deep prefetch), 256 thr (8 warps),
// warp tile 32x64. Stage: X[128][72]h (18432B) | W same. One barrier/iter.
// ===========================================================================
#define BK     64
#define XS_LD  72
#define STG_B  36864                  // per-stage bytes (X 18432 + W 18432)
#define GEMM_DSMEM (2*STG_B)          // 73728

__device__ __forceinline__ void gemm_body(
    char* sm, const __half* __restrict__ X, const __half* __restrict__ W,
    const float* __restrict__ bias, void* __restrict__ outv, int out_half,
    int m0, int n0)
{
    const uint32_t smu = smem_u32(sm);
    const int tid = threadIdx.x;
    const int wid = tid >> 5, lane = tid & 31;
    const int wm = wid >> 1, wn = wid & 1;

    wmma::fragment<wmma::accumulator,16,16,16,float> acc[2][4];
#pragma unroll
    for (int mi = 0; mi < 2; mi++)
#pragma unroll
        for (int ni = 0; ni < 4; ni++) wmma::fill_fragment(acc[mi][ni], 0.f);

    // loader: 2048 x 16B chunks per stage (X 1024 + W 1024), 8 per thread
    auto issue = [&](int it) {
        const int kb = it * BK;
        const int slot = it & 1;
#pragma unroll
        for (int c = 0; c < 8; c++) {
            int idx = tid + c * 256;       // 0..2047
            int isw = idx >> 10;           // 0:X 1:W
            int r   = (idx >> 3) & 127;
            int ch  = idx & 7;
            const __half* src = (isw ? W : X)
                + (size_t)((isw ? n0 : m0) + r) * DMODEL + kb + ch * 8;
            uint32_t dst = smu + slot * STG_B + isw * 18432 + r * 144 + ch * 16;
            CP_ASYNC16(dst, src);
        }
        CP_COMMIT();
    };

    issue(0);
    const int NIT = DMODEL / BK;           // 16
    for (int it = 0; it < NIT; it++) {
        CP_WAIT(0);                        // stage it landed (own groups)
        __syncthreads();                   // visible to all; slot (it+1)&1 reusable
        if (it + 1 < NIT) issue(it + 1);   // overlaps with mma below

        __half* Xs = (__half*)(sm + (it & 1) * STG_B);
        __half* Ws = (__half*)(sm + (it & 1) * STG_B + 18432);
#pragma unroll
        for (int ks = 0; ks < 4; ks++) {
            wmma::fragment<wmma::matrix_a,16,16,16,__half,wmma::row_major> a[2];
            wmma::fragment<wmma::matrix_b,16,16,16,__half,wmma::col_major> bf[4];
#pragma unroll
            for (int mi = 0; mi < 2; mi++)
                wmma::load_matrix_sync(a[mi], &Xs[(wm*32 + mi*16)*XS_LD + ks*16], XS_LD);
#pragma unroll
            for (int ni = 0; ni < 4; ni++)
                wmma::load_matrix_sync(bf[ni], &Ws[(wn*64 + ni*16)*XS_LD + ks*16], XS_LD);
#pragma unroll
            for (int mi = 0; mi < 2; mi++)
#pragma unroll
                for (int ni = 0; ni < 4; ni++)
                    wmma::mma_sync(acc[mi][ni], a[mi], bf[ni], acc[mi][ni]);
        }
    }
    __syncthreads();   // all mma reads done; reuse smem as epilogue patches

    float* pp = (float*)sm + wid * 16 * 68;
#pragma unroll
    for (int mi = 0; mi < 2; mi++) {
#pragma unroll
        for (int ni = 0; ni < 4; ni++)
            wmma::store_matrix_sync(pp + ni*16, acc[mi][ni], 68, wmma::mem_row_major);
        __syncwarp();
#pragma unroll
        for (int l = 0; l < 8; l++) {
            int f = lane + l * 32;
            int r = f >> 4, c4 = f & 15;
            int m = m0 + wm*32 + mi*16 + r;
            int n = n0 + wn*64 + c4*4;
            float4 v = *(float4*)&pp[r*68 + c4*4];
            float4 bb = *(const float4*)&bias[n];
            v.x += bb.x; v.y += bb.y; v.z += bb.z; v.w += bb.w;
            if (out_half) {
                __half2 h0 = __floats2half2_rn(v.x, v.y);
                __half2 h1 = __floats2half2_rn(v.z, v.w);
                uint2 u; u.x = *(uint32_t*)&h0; u.y = *(uint32_t*)&h1;
                *(uint2*)&((__half*)outv)[(size_t)m * DMODEL + n] = u;
            } else {
                *(float4*)&((float*)outv)[(size_t)m * DMODEL + n] = v;
            }
        }
        __syncwarp();
    }
}

// fused Q/K/V projection, persistent over z: grid (8, 32), 1 wave @ 2 CTA/SM
__global__ __launch_bounds__(256, 2)
void gemm_qkv(const float* __restrict__ bq, const float* __restrict__ bk,
              const float* __restrict__ bv)
{
    extern __shared__ __align__(16) char sm[];
#pragma unroll 1
    for (int z = 0; z < 3; z++) {
        const __half* X = (z == 0) ? g_xq : (z == 1) ? g_xk : g_xv;
        const __half* W = (z == 0) ? g_wq : (z == 1) ? g_wk : g_wv;
        const float*  B = (z == 0) ? bq   : (z == 1) ? bk   : bv;
        __half* O      = (z == 0) ? g_Q  : (z == 1) ? g_K  : g_V;
        if (z) __syncthreads();   // patch reads done before stage-0 refill
        gemm_body(sm, X, W, B, O, 1, blockIdx.y * 128, blockIdx.x * 128);
    }
}

// output projection: ctx(half) @ Wo^T + bo -> f32 out
__global__ __launch_bounds__(256, 2)
void gemm_out(const float* __restrict__ bo, float* __restrict__ out)
{
    extern __shared__ __align__(16) char sm[];
    gemm_body(sm, g_ctx, g_wo, bo, out, 0, blockIdx.y * 128, blockIdx.x * 128);
}

// ===========================================================================
// Flash attention: raw mma.m16n8k16, register softmax/P, cp.async K/V,
// preloaded bias window. PERSISTENT: each block processes 2 work units
// (grid 256 = single wave at 2 CTA/SM). Unit = 2*bx+u -> (qt = unit&15,
// bh = unit>>4): consecutive q-tiles share bh (K/V L2-hot).
// ===========================================================================
#define KV_STG 18432
#define NTILES (SLEN/64)

__global__ __launch_bounds__(256, 2)
void attn_kernel(const float* __restrict__ rel_table)
{
    __shared__ __align__(16) float  sball[2176];
    __shared__ __align__(16) __half kvbuf[2 * KV_STG / 2];

    const int tid  = threadIdx.x;
    const int wid  = tid >> 5, lane = tid & 31;
    const uint32_t kvu = smem_u32(kvbuf);

    const int g  = lane >> 2, tg = lane & 3;
    const int lr  = lane & 7;
    const int sel = lane >> 3;            // 0..3

#pragma unroll 1
    for (int u = 0; u < 2; u++) {
        const int unit = blockIdx.x * 2 + u;
        const int q0   = (unit & 15) * 128;
        const int bh   = unit >> 4;
        const int h    = bh & (HEADS - 1);
        const int b    = bh >> 4;
        const int col0 = h * DK;

        __syncthreads();   // prior unit's smem reads fully retired

        for (int i = tid; i < 2176; i += 256) {
            int idx = q0 + i;
            idx = min(max(idx, 0), NREL - 1);
            sball[i] = __ldg(&rel_table[idx * HEADS + h]);
        }

        // stage Q (128 rows x 64 halves) into stage-0 area, then ldmatrix
#pragma unroll
        for (int c = 0; c < 4; c++) {
            int idx = tid + c * 256;
            int r = idx >> 3, c16 = idx & 7;
            *(uint4*)((char*)kvbuf + r*144 + c16*16) =
                *(const uint4*)&g_Q[(size_t)((q0 + r)*BATCH + b) * DMODEL + col0 + c16*8];
        }
        __syncthreads();

        uint32_t Qa[4][4];
        {
            int rsel = lane & 15, csel = (lane >> 4) & 1;
#pragma unroll
            for (int kc = 0; kc < 4; kc++) {
                uint32_t addr = kvu + (wid*16 + rsel)*144 + kc*32 + csel*16;
                LDSM_X4(Qa[kc][0], Qa[kc][1], Qa[kc][2], Qa[kc][3], addr);
            }
        }
        __syncthreads();   // Q reads done; stage 0 free for prefetch

        auto prefetch = [&](int t, int stg) {
            int k0 = t * 64;
#pragma unroll
            for (int c = 0; c < 4; c++) {
                int idx = tid + c * 256;
                int isv = idx >> 9;
                int r   = (idx >> 3) & 63;
                int c16 = idx & 7;
                const __half* src = (isv ? g_V : g_K)
                    + (size_t)((k0 + r)*BATCH + b) * DMODEL + col0 + c16*8;
                uint32_t dst = kvu + stg*KV_STG + isv*9216 + r*144 + c16*16;
                CP_ASYNC16(dst, src);
            }
        };

        prefetch(0, 0);
        CP_COMMIT();

        const int row0 = wid*16 + g;

        float Oacc[8][4];
#pragma unroll
        for (int nt = 0; nt < 8; nt++)
#pragma unroll
            for (int e = 0; e < 4; e++) Oacc[nt][e] = 0.f;
        float lrun0 = 0.f, lrun1 = 0.f;

        for (int t = 0; t < NTILES; t++) {
            const int st = t & 1;
            if (t + 1 < NTILES) { prefetch(t + 1, (t + 1) & 1); CP_COMMIT(); CP_WAIT(1); }
            else                { CP_WAIT(0); }
            __syncthreads();

            const uint32_t kb = kvu + st*KV_STG;
            const uint32_t vb = kb + 9216;

            float sacc[8][4];
#pragma unroll
            for (int nt = 0; nt < 8; nt++)
#pragma unroll
                for (int e = 0; e < 4; e++) sacc[nt][e] = 0.f;

#pragma unroll
            for (int kc = 0; kc < 4; kc++) {
#pragma unroll
                for (int tp = 0; tp < 4; tp++) {
                    uint32_t b0, b1, b2, b3;
                    uint32_t addr = kb + ((tp*2 + (sel >> 1))*8 + lr)*144
                                  + kc*32 + (sel & 1)*16;
                    LDSM_X4(b0, b1, b2, b3, addr);
                    MMA16816(sacc[tp*2],     Qa[kc], b0, b1);
                    MMA16816(sacc[tp*2 + 1], Qa[kc], b2, b3);
                }
            }

            const int dconst = 2047 - t*64;
            uint32_t Pa[4][4];
#pragma unroll
            for (int nt = 0; nt < 8; nt++) {
                int colL = nt*8 + 2*tg;
                int d00  = row0 - colL + dconst;
                float v0 = fmaf(sacc[nt][0], SCALE_F, sball[d00])     - EXP_OFF;
                float v1 = fmaf(sacc[nt][1], SCALE_F, sball[d00 - 1]) - EXP_OFF;
                float v2 = fmaf(sacc[nt][2], SCALE_F, sball[d00 + 8]) - EXP_OFF;
                float v3 = fmaf(sacc[nt][3], SCALE_F, sball[d00 + 7]) - EXP_OFF;
                __half2 h01 = __floats2half2_rn(__expf(v0), __expf(v1));
                __half2 h23 = __floats2half2_rn(__expf(v2), __expf(v3));
                float2 f01 = __half22float2(h01);
                float2 f23 = __half22float2(h23);
                lrun0 += f01.x + f01.y;
                lrun1 += f23.x + f23.y;
                Pa[nt >> 1][(nt & 1)*2 + 0] = *(uint32_t*)&h01;
                Pa[nt >> 1][(nt & 1)*2 + 1] = *(uint32_t*)&h23;
            }

#pragma unroll
            for (int kc = 0; kc < 4; kc++) {
#pragma unroll
                for (int tp = 0; tp < 4; tp++) {
                    uint32_t b0, b1, b2, b3;
                    uint32_t addr = vb + (kc*16 + (sel & 1)*8 + lr)*144
                                  + (tp*2 + (sel >> 1))*16;
                    LDSM_X4_T(b0, b1, b2, b3, addr);
                    MMA16816(Oacc[tp*2],     Pa[kc], b0, b1);
                    MMA16816(Oacc[tp*2 + 1], Pa[kc], b2, b3);
                }
            }
            __syncthreads();
        }

        lrun0 += __shfl_xor_sync(0xffffffffu, lrun0, 1);
        lrun0 += __shfl_xor_sync(0xffffffffu, lrun0, 2);
        lrun1 += __shfl_xor_sync(0xffffffffu, lrun1, 1);
        lrun1 += __shfl_xor_sync(0xffffffffu, lrun1, 2);
        const float inv0 = 1.f / lrun0;
        const float inv1 = 1.f / lrun1;

#pragma unroll
        for (int nt = 0; nt < 8; nt++) {
            __half2 h0 = __floats2half2_rn(Oacc[nt][0]*inv0, Oacc[nt][1]*inv0);
            __half2 h1 = __floats2half2_rn(Oacc[nt][2]*inv1, Oacc[nt][3]*inv1);
            size_t base = (size_t)((q0 + row0)*BATCH + b) * DMODEL + col0 + nt*8 + 2*tg;
            *(uint32_t*)&g_ctx[base] = *(uint32_t*)&h0;
            *(uint32_t*)&g_ctx[base + 8*BATCH*DMODEL] = *(uint32_t*)&h1;
        }
    }
}

// ---------------------------------------------------------------------------
extern "C" void kernel_launch(void* const* d_in, const int* in_sizes, int n_in,
                              void* d_out, int out_size)
{
    const float* query = (const float*)d_in[0];
    const float* key   = (const float*)d_in[1];
    const float* value = (const float*)d_in[2];
    const float* Wq    = (const float*)d_in[3];
    const float* bq    = (const float*)d_in[4];
    const float* Wk    = (const float*)d_in[5];
    const float* bk    = (const float*)d_in[6];
    const float* Wv    = (const float*)d_in[7];
    const float* bv    = (const float*)d_in[8];
    const float* Wo    = (const float*)d_in[9];
    const float* bo    = (const float*)d_in[10];
    const float* rel   = (const float*)d_in[11];
    float* out = (float*)d_out;

    void *pxq, *pxk, *pxv, *pwq, *pwk, *pwv, *pwo;
    cudaGetSymbolAddress(&pxq, g_xq);
    cudaGetSymbolAddress(&pxk, g_xk);
    cudaGetSymbolAddress(&pxv, g_xv);
    cudaGetSymbolAddress(&pwq, g_wq);
    cudaGetSymbolAddress(&pwk, g_wk);
    cudaGetSymbolAddress(&pwv, g_wv);
    cudaGetSymbolAddress(&pwo, g_wo);

    cudaFuncSetAttribute(gemm_qkv, cudaFuncAttributeMaxDynamicSharedMemorySize, GEMM_DSMEM);
    cudaFuncSetAttribute(gemm_out, cudaFuncAttributeMaxDynamicSharedMemorySize, GEMM_DSMEM);

    const int NIN = MROWS * DMODEL;      // 4M
    const int NW  = DMODEL * DMODEL;     // 1M

    cvt_f2h<<<NIN/8/256, 256>>>(query, (__half*)pxq, NIN);
    cvt_f2h<<<NIN/8/256, 256>>>(key,   (__half*)pxk, NIN);
    cvt_f2h<<<NIN/8/256, 256>>>(value, (__half*)pxv, NIN);
    cvt_f2h<<<NW/8/256,  256>>>(Wq,    (__half*)pwq, NW);
    cvt_f2h<<<NW/8/256,  256>>>(Wk,    (__half*)pwk, NW);
    cvt_f2h<<<NW/8/256,  256>>>(Wv,    (__half*)pwv, NW);
    cvt_f2h<<<NW/8/256,  256>>>(Wo,    (__half*)pwo, NW);

    gemm_qkv<<<dim3(DMODEL/128, MROWS/128), 256, GEMM_DSMEM>>>(bq, bk, bv);

    attn_kernel<<<256, 256>>>(rel);

    gemm_out<<<dim3(DMODEL/128, MROWS/128), 256, GEMM_DSMEM>>>(bo, out);
}